// round 1
// baseline (speedup 1.0000x reference)
#include <cuda_runtime.h>
#include <cuda_bf16.h>
#include <math.h>

// Problem constants
#define B_  2
#define S_  2048
#define D_  2048
#define H_  16
#define HD_ 128
#define M_  (B_ * S_)          // 4096 rows for projections
#define PER_TENSOR (B_ * S_ * D_)   // 8388608

// ---------------------------------------------------------------------------
// Scratch (device globals — no allocation allowed)
// ---------------------------------------------------------------------------
__device__ float g_scratch[PER_TENSOR];  // projection output (B*S, D)
__device__ float g_q[PER_TENSOR];        // Q after rope, (B,H,S,hd)
__device__ float g_o[PER_TENSOR];        // attention out, (B,S,D) layout

// ---------------------------------------------------------------------------
// SGEMM: C[m,n] = sum_k A[m,k] * W[n,k]   (A: MxK row-major, W: NxK row-major)
// BM=BN=128, BK=16, 256 threads, 8x8 microtile
// ---------------------------------------------------------------------------
#define BM 128
#define BN 128
#define BK 16

__global__ __launch_bounds__(256, 2)
void sgemm_xwT(const float* __restrict__ A, const float* __restrict__ W,
               float* __restrict__ C, int M, int N, int K) {
    __shared__ float As[BK][BM];
    __shared__ float Bs[BK][BN];

    const int tid = threadIdx.x;
    const int tx = tid % 16;       // 0..15 -> col group
    const int ty = tid / 16;       // 0..15 -> row group
    const int rowBase = blockIdx.y * BM;
    const int colBase = blockIdx.x * BN;

    // loader mapping: each thread loads float4 along K
    const int ldRow = tid / 4;          // 0..63
    const int ldCol = (tid % 4) * 4;    // 0,4,8,12

    float acc[8][8];
#pragma unroll
    for (int i = 0; i < 8; i++)
#pragma unroll
        for (int j = 0; j < 8; j++) acc[i][j] = 0.f;

    for (int k0 = 0; k0 < K; k0 += BK) {
#pragma unroll
        for (int r = 0; r < BM; r += 64) {
            float4 a = *(const float4*)&A[(size_t)(rowBase + ldRow + r) * K + k0 + ldCol];
            As[ldCol + 0][ldRow + r] = a.x;
            As[ldCol + 1][ldRow + r] = a.y;
            As[ldCol + 2][ldRow + r] = a.z;
            As[ldCol + 3][ldRow + r] = a.w;
        }
#pragma unroll
        for (int r = 0; r < BN; r += 64) {
            float4 b = *(const float4*)&W[(size_t)(colBase + ldRow + r) * K + k0 + ldCol];
            Bs[ldCol + 0][ldRow + r] = b.x;
            Bs[ldCol + 1][ldRow + r] = b.y;
            Bs[ldCol + 2][ldRow + r] = b.z;
            Bs[ldCol + 3][ldRow + r] = b.w;
        }
        __syncthreads();

#pragma unroll
        for (int kk = 0; kk < BK; kk++) {
            float af[8], bf[8];
            *(float4*)&af[0] = *(const float4*)&As[kk][ty * 8];
            *(float4*)&af[4] = *(const float4*)&As[kk][ty * 8 + 4];
            *(float4*)&bf[0] = *(const float4*)&Bs[kk][tx * 8];
            *(float4*)&bf[4] = *(const float4*)&Bs[kk][tx * 8 + 4];
#pragma unroll
            for (int i = 0; i < 8; i++)
#pragma unroll
                for (int j = 0; j < 8; j++)
                    acc[i][j] += af[i] * bf[j];
        }
        __syncthreads();
    }

#pragma unroll
    for (int i = 0; i < 8; i++) {
        float* crow = &C[(size_t)(rowBase + ty * 8 + i) * N + colBase + tx * 8];
#pragma unroll
        for (int j = 0; j < 8; j += 4) {
            float4 v = make_float4(acc[i][j], acc[i][j + 1], acc[i][j + 2], acc[i][j + 3]);
            *(float4*)&crow[j] = v;
        }
    }
}

// ---------------------------------------------------------------------------
// RoPE + transpose: X (B*S, D) -> out (B,H,S,hd) with rope applied
// one thread per (b,s,h,dpair)
// ---------------------------------------------------------------------------
__global__ void rope_transpose(const float* __restrict__ X,
                               const float* __restrict__ cosT,
                               const float* __restrict__ sinT,
                               float* __restrict__ out) {
    int idx = blockIdx.x * blockDim.x + threadIdx.x;   // B*S*H*64 = 4194304
    if (idx >= B_ * S_ * H_ * (HD_ / 2)) return;
    int dp = idx & 63;
    int h  = (idx >> 6) & 15;
    int s  = (idx >> 10) & (S_ - 1);
    int b  = idx >> 21;

    const float* xr = X + (size_t)(b * S_ + s) * D_ + h * HD_;
    float x1 = xr[2 * dp];
    float x2 = xr[2 * dp + 1];
    float c  = cosT[s * (HD_ / 2) + dp];
    float sn = sinT[s * (HD_ / 2) + dp];

    float* orow = out + ((size_t)(b * H_ + h) * S_ + s) * HD_;
    orow[2 * dp]     = x1 * c - x2 * sn;
    orow[2 * dp + 1] = x1 * sn + x2 * c;
}

// ---------------------------------------------------------------------------
// Transpose only (for V): X (B*S, D) -> out (B,H,S,hd)
// one thread per float4
// ---------------------------------------------------------------------------
__global__ void transpose_bshd(const float* __restrict__ X, float* __restrict__ out) {
    int idx = blockIdx.x * blockDim.x + threadIdx.x;   // PER_TENSOR/4 = 2097152
    if (idx >= PER_TENSOR / 4) return;
    int c4 = idx & 31;                  // 128/4
    int h  = (idx >> 5) & 15;
    int s  = (idx >> 9) & (S_ - 1);
    int b  = idx >> 20;
    float4 v = *(const float4*)&X[(size_t)(b * S_ + s) * D_ + h * HD_ + c4 * 4];
    *(float4*)&out[((size_t)(b * H_ + h) * S_ + s) * HD_ + c4 * 4] = v;
}

// ---------------------------------------------------------------------------
// Flash attention (causal), fp32.
// Q,K,V: (B*H, S, 128). O written as (B, S, H*128).
// Block: 256 threads = 8 warps; warp w owns query row blockIdx.x*8 + w.
// KV tiles of 32 rows in smem (rows padded to 132 floats -> conflict-free f4).
// ---------------------------------------------------------------------------
__global__ __launch_bounds__(256, 2)
void flash_attn(const float* __restrict__ Q, const float* __restrict__ K,
                const float* __restrict__ V, float* __restrict__ O) {
    const int bh = blockIdx.y;
    const int b = bh / H_;
    const int h = bh % H_;
    const int warp = threadIdx.x >> 5;
    const int lane = threadIdx.x & 31;
    const int qr = blockIdx.x * 8 + warp;

    __shared__ float sQ[8][128];
    __shared__ float sK[32][132];
    __shared__ float sV[32][132];

    const float scale = 0.08838834764831845f;  // 1/sqrt(128)
    const float* Qb = Q + (size_t)bh * S_ * HD_;
    const float* Kb = K + (size_t)bh * S_ * HD_;
    const float* Vb = V + (size_t)bh * S_ * HD_;

    // load 8 query rows (pre-scaled)
    {
        int r = threadIdx.x >> 5;
        int c = (threadIdx.x & 31) * 4;
        float4 q4 = *(const float4*)&Qb[(size_t)(blockIdx.x * 8 + r) * HD_ + c];
        sQ[r][c + 0] = q4.x * scale;
        sQ[r][c + 1] = q4.y * scale;
        sQ[r][c + 2] = q4.z * scale;
        sQ[r][c + 3] = q4.w * scale;
    }

    float m = -INFINITY, l = 0.f;
    float4 acc = make_float4(0.f, 0.f, 0.f, 0.f);

    const int maxRow = blockIdx.x * 8 + 7;
    const int nTiles = maxRow / 32 + 1;

    for (int t = 0; t < nTiles; t++) {
        const int j0 = t * 32;
        // cooperative tile load: 32x128 K and V
        {
            int r = threadIdx.x >> 3;            // 0..31
            int c = (threadIdx.x & 7) * 16;      // 0..112 step 16
#pragma unroll
            for (int i = 0; i < 16; i += 4) {
                *(float4*)&sK[r][c + i] = *(const float4*)&Kb[(size_t)(j0 + r) * HD_ + c + i];
                *(float4*)&sV[r][c + i] = *(const float4*)&Vb[(size_t)(j0 + r) * HD_ + c + i];
            }
        }
        __syncthreads();

        if (j0 <= qr) {
            const int j = j0 + lane;
            float s = -INFINITY;
            if (j <= qr) {
                s = 0.f;
#pragma unroll
                for (int d = 0; d < 128; d += 4) {
                    float4 q4 = *(const float4*)&sQ[warp][d];
                    float4 k4 = *(const float4*)&sK[lane][d];
                    s += q4.x * k4.x + q4.y * k4.y + q4.z * k4.z + q4.w * k4.w;
                }
            }
            float tmax = s;
#pragma unroll
            for (int o = 16; o; o >>= 1) tmax = fmaxf(tmax, __shfl_xor_sync(0xffffffffu, tmax, o));
            const float mn = fmaxf(m, tmax);
            const float p = (s == -INFINITY) ? 0.f : __expf(s - mn);
            const float corr = (m == -INFINITY) ? 0.f : __expf(m - mn);
            float psum = p;
#pragma unroll
            for (int o = 16; o; o >>= 1) psum += __shfl_xor_sync(0xffffffffu, psum, o);
            l = l * corr + psum;
            acc.x *= corr; acc.y *= corr; acc.z *= corr; acc.w *= corr;
#pragma unroll
            for (int jj = 0; jj < 32; jj++) {
                float pj = __shfl_sync(0xffffffffu, p, jj);
                float4 v4 = *(const float4*)&sV[jj][lane * 4];
                acc.x += pj * v4.x;
                acc.y += pj * v4.y;
                acc.z += pj * v4.z;
                acc.w += pj * v4.w;
            }
            m = mn;
        }
        __syncthreads();
    }

    const float inv = 1.f / l;
    float4 o4 = make_float4(acc.x * inv, acc.y * inv, acc.z * inv, acc.w * inv);
    *(float4*)&O[(size_t)(b * S_ + qr) * D_ + h * HD_ + lane * 4] = o4;
}

// ---------------------------------------------------------------------------
// Launcher
// ---------------------------------------------------------------------------
extern "C" void kernel_launch(void* const* d_in, const int* in_sizes, int n_in,
                              void* d_out, int out_size) {
    const float* hs   = (const float*)d_in[0];
    const float* cosT = (const float*)d_in[1];
    const float* sinT = (const float*)d_in[2];
    const float* wq   = (const float*)d_in[3];
    const float* wk   = (const float*)d_in[4];
    const float* wv   = (const float*)d_in[5];
    const float* wo   = (const float*)d_in[6];

    float* out  = (float*)d_out;                 // (B,S,D)
    float* kout = out + (size_t)PER_TENSOR;      // (B,H,S,hd)
    float* vout = out + (size_t)2 * PER_TENSOR;  // (B,H,S,hd)

    float* scratch = nullptr;
    float* qbuf = nullptr;
    float* obuf = nullptr;
    cudaGetSymbolAddress((void**)&scratch, g_scratch);
    cudaGetSymbolAddress((void**)&qbuf, g_q);
    cudaGetSymbolAddress((void**)&obuf, g_o);

    dim3 gemmGrid(D_ / BN, M_ / BM);   // (16, 32)
    dim3 gemmBlock(256);
    dim3 ropeGrid((B_ * S_ * H_ * (HD_ / 2) + 255) / 256);
    dim3 transGrid((PER_TENSOR / 4 + 255) / 256);
    dim3 attnGrid(S_ / 8, B_ * H_);    // (256, 32)

    // Q projection + rope
    sgemm_xwT<<<gemmGrid, gemmBlock>>>(hs, wq, scratch, M_, D_, D_);
    rope_transpose<<<ropeGrid, 256>>>(scratch, cosT, sinT, qbuf);
    // K projection + rope (writes directly into output k region)
    sgemm_xwT<<<gemmGrid, gemmBlock>>>(hs, wk, scratch, M_, D_, D_);
    rope_transpose<<<ropeGrid, 256>>>(scratch, cosT, sinT, kout);
    // V projection + transpose (writes directly into output v region)
    sgemm_xwT<<<gemmGrid, gemmBlock>>>(hs, wv, scratch, M_, D_, D_);
    transpose_bshd<<<transGrid, 256>>>(scratch, vout);
    // causal attention
    flash_attn<<<attnGrid, 256>>>(qbuf, kout, vout, obuf);
    // output projection -> first output region
    sgemm_xwT<<<gemmGrid, gemmBlock>>>(obuf, wo, out, M_, D_, D_);
}

// round 3
// speedup vs baseline: 1.3952x; 1.3952x over previous
#include <cuda_runtime.h>
#include <cuda_bf16.h>
#include <math.h>
#include <cstdint>

// Problem constants
#define B_  2
#define S_  2048
#define D_  2048
#define H_  16
#define HD_ 128
#define M_  (B_ * S_)               // 4096
#define PER_TENSOR (B_ * S_ * D_)   // 8388608

// ---------------------------------------------------------------------------
// Scratch (device globals — no allocation allowed)
// ---------------------------------------------------------------------------
__device__ float g_scratch[PER_TENSOR];  // projection output (B*S, D)
__device__ float g_q[PER_TENSOR];        // Q after rope, (B,H,S,hd)
__device__ float g_o[PER_TENSOR];        // attention out, (B,S,D) layout

// ---------------------------------------------------------------------------
// tf32 mma.sync GEMM:  C[m,n] = sum_k A[m,k] * W[n,k]
// A: (M x K) row-major fp32, W: (N x K) row-major fp32. fp32 accumulate.
// Tile 128x128x32, 256 threads (8 warps, warp tile 64x32), 3-stage cp.async.
// tf32 RN rounding applied in-register on fragments.
// ---------------------------------------------------------------------------
#define BM 128
#define BN 128
#define BK 32
#define NSTAGE 3
#define STAGE_FLOATS (2 * BM * BK)          // A tile + B tile = 8192 floats
#define GEMM_SMEM (NSTAGE * STAGE_FLOATS * 4)  // 98304 bytes

#define CVT_TF32(x) asm volatile("cvt.rn.tf32.f32 %0, %1;" : "=r"(x) : "r"(x))

#define LDMX4(r0, r1, r2, r3, addr)                                           \
    asm volatile("ldmatrix.sync.aligned.m8n8.x4.shared.b16 {%0,%1,%2,%3}, [%4];" \
                 : "=r"(r0), "=r"(r1), "=r"(r2), "=r"(r3) : "r"(addr))

#define MMA_TF32(d, a, b0v, b1v)                                              \
    asm volatile("mma.sync.aligned.m16n8k8.row.col.f32.tf32.tf32.f32 "        \
                 "{%0,%1,%2,%3}, {%4,%5,%6,%7}, {%8,%9}, {%0,%1,%2,%3};"      \
                 : "+f"(d[0]), "+f"(d[1]), "+f"(d[2]), "+f"(d[3])             \
                 : "r"(a[0]), "r"(a[1]), "r"(a[2]), "r"(a[3]),                \
                   "r"(b0v), "r"(b1v))

__global__ __launch_bounds__(256, 1)
void gemm_tf32(const float* __restrict__ A, const float* __restrict__ W,
               float* __restrict__ C, int M, int N, int K) {
    extern __shared__ float smem[];
    const uint32_t sbase = (uint32_t)__cvta_generic_to_shared(smem);

    const int tid = threadIdx.x;
    const int lane = tid & 31;
    const int warp = tid >> 5;
    const int wm = warp >> 2;        // 0..1  -> 64-row slab
    const int wn = warp & 3;         // 0..3  -> 32-col slab

    const int rowBase = blockIdx.y * BM;
    const int colBase = blockIdx.x * BN;

    // ---- cp.async loader mapping: each thread loads 4 x 16B for A, 4 for B
    const int ldRow = tid >> 1;              // 0..127
    const int ldC0 = (tid & 1) * 4;          // chunk 0..3 or 4..7
    const float* Ag = A + (size_t)(rowBase + ldRow) * K;
    const float* Wg = W + (size_t)(colBase + ldRow) * K;

    const int KT = K / BK;

    auto load_stage = [&](int kt, int stg) {
        uint32_t sA = sbase + stg * (STAGE_FLOATS * 4);
        uint32_t sB = sA + BM * BK * 4;
        const float* ga = Ag + kt * BK + ldC0 * 4;
        const float* gb = Wg + kt * BK + ldC0 * 4;
#pragma unroll
        for (int c = 0; c < 4; c++) {
            int ch = ldC0 + c;
            uint32_t off = (uint32_t)(ldRow * 128 + ((ch ^ (ldRow & 7)) << 4));
            uint64_t gA = __cvta_generic_to_global(ga + c * 4);
            uint64_t gB = __cvta_generic_to_global(gb + c * 4);
            asm volatile("cp.async.cg.shared.global [%0], [%1], 16;" :: "r"(sA + off), "l"(gA));
            asm volatile("cp.async.cg.shared.global [%0], [%1], 16;" :: "r"(sB + off), "l"(gB));
        }
    };

    // ldmatrix per-thread address components
    const int aRowLoc = (lane & 7) + (((lane >> 3) & 1) << 3);  // row within 16
    const int aChunkAdd = lane >> 4;                             // 0/1 -> k+4
    const int bRowLoc = lane & 7;
    const int bChunkAdd = lane >> 3;                             // 0..3

    float acc[4][4][4];
#pragma unroll
    for (int i = 0; i < 4; i++)
#pragma unroll
        for (int j = 0; j < 4; j++)
#pragma unroll
            for (int r = 0; r < 4; r++) acc[i][j][r] = 0.f;

    // prologue
    load_stage(0, 0);
    asm volatile("cp.async.commit_group;" ::: "memory");
    load_stage(1, 1);
    asm volatile("cp.async.commit_group;" ::: "memory");

    for (int kt = 0; kt < KT; kt++) {
        asm volatile("cp.async.wait_group 1;" ::: "memory");
        __syncthreads();

        const int stg = kt % NSTAGE;
        const uint32_t sA = sbase + stg * (STAGE_FLOATS * 4);
        const uint32_t sB = sA + BM * BK * 4;

#pragma unroll
        for (int p = 0; p < 2; p++) {        // k-step pairs (k = 16 per pair)
            uint32_t b[4][4];
#pragma unroll
            for (int nt = 0; nt < 4; nt++) {
                int row = wn * 32 + nt * 8 + bRowLoc;
                int ch = p * 4 + bChunkAdd;
                uint32_t addr = sB + row * 128 + ((ch ^ (row & 7)) << 4);
                LDMX4(b[nt][0], b[nt][1], b[nt][2], b[nt][3], addr);
#pragma unroll
                for (int r = 0; r < 4; r++) CVT_TF32(b[nt][r]);
            }
#pragma unroll
            for (int kh = 0; kh < 2; kh++) {
                const int ks = p * 2 + kh;
                uint32_t a[4][4];
#pragma unroll
                for (int mt = 0; mt < 4; mt++) {
                    int row = wm * 64 + mt * 16 + aRowLoc;
                    int ch = ks * 2 + aChunkAdd;
                    uint32_t addr = sA + row * 128 + ((ch ^ (row & 7)) << 4);
                    LDMX4(a[mt][0], a[mt][1], a[mt][2], a[mt][3], addr);
#pragma unroll
                    for (int r = 0; r < 4; r++) CVT_TF32(a[mt][r]);
                }
#pragma unroll
                for (int mt = 0; mt < 4; mt++)
#pragma unroll
                    for (int nt = 0; nt < 4; nt++)
                        MMA_TF32(acc[mt][nt], a[mt], b[nt][kh * 2], b[nt][kh * 2 + 1]);
            }
        }

        if (kt + 2 < KT) load_stage(kt + 2, (kt + 2) % NSTAGE);
        asm volatile("cp.async.commit_group;" ::: "memory");
    }

    // epilogue
    const int erow = lane >> 2;
    const int ecol = (lane & 3) * 2;
#pragma unroll
    for (int mt = 0; mt < 4; mt++) {
#pragma unroll
        for (int nt = 0; nt < 4; nt++) {
            int r0 = rowBase + wm * 64 + mt * 16 + erow;
            int c0 = colBase + wn * 32 + nt * 8 + ecol;
            *(float2*)&C[(size_t)r0 * N + c0] = make_float2(acc[mt][nt][0], acc[mt][nt][1]);
            *(float2*)&C[(size_t)(r0 + 8) * N + c0] = make_float2(acc[mt][nt][2], acc[mt][nt][3]);
        }
    }
}

// ---------------------------------------------------------------------------
// RoPE + transpose: X (B*S, D) -> out (B,H,S,hd) with rope applied
// ---------------------------------------------------------------------------
__global__ void rope_transpose(const float* __restrict__ X,
                               const float* __restrict__ cosT,
                               const float* __restrict__ sinT,
                               float* __restrict__ out) {
    int idx = blockIdx.x * blockDim.x + threadIdx.x;
    if (idx >= B_ * S_ * H_ * (HD_ / 2)) return;
    int dp = idx & 63;
    int h  = (idx >> 6) & 15;
    int s  = (idx >> 10) & (S_ - 1);
    int b  = idx >> 21;

    const float* xr = X + (size_t)(b * S_ + s) * D_ + h * HD_;
    float x1 = xr[2 * dp];
    float x2 = xr[2 * dp + 1];
    float c  = cosT[s * (HD_ / 2) + dp];
    float sn = sinT[s * (HD_ / 2) + dp];

    float* orow = out + ((size_t)(b * H_ + h) * S_ + s) * HD_;
    orow[2 * dp]     = x1 * c - x2 * sn;
    orow[2 * dp + 1] = x1 * sn + x2 * c;
}

// ---------------------------------------------------------------------------
// Transpose only (for V): X (B*S, D) -> out (B,H,S,hd)
// ---------------------------------------------------------------------------
__global__ void transpose_bshd(const float* __restrict__ X, float* __restrict__ out) {
    int idx = blockIdx.x * blockDim.x + threadIdx.x;
    if (idx >= PER_TENSOR / 4) return;
    int c4 = idx & 31;
    int h  = (idx >> 5) & 15;
    int s  = (idx >> 9) & (S_ - 1);
    int b  = idx >> 20;
    float4 v = *(const float4*)&X[(size_t)(b * S_ + s) * D_ + h * HD_ + c4 * 4];
    *(float4*)&out[((size_t)(b * H_ + h) * S_ + s) * HD_ + c4 * 4] = v;
}

// ---------------------------------------------------------------------------
// Flash attention (causal), fp32 — unchanged (passing, ~isolated change rule)
// ---------------------------------------------------------------------------
__global__ __launch_bounds__(256, 2)
void flash_attn(const float* __restrict__ Q, const float* __restrict__ K,
                const float* __restrict__ V, float* __restrict__ O) {
    const int bh = blockIdx.y;
    const int b = bh / H_;
    const int h = bh % H_;
    const int warp = threadIdx.x >> 5;
    const int lane = threadIdx.x & 31;
    const int qr = blockIdx.x * 8 + warp;

    __shared__ float sQ[8][128];
    __shared__ float sK[32][132];
    __shared__ float sV[32][132];

    const float scale = 0.08838834764831845f;
    const float* Qb = Q + (size_t)bh * S_ * HD_;
    const float* Kb = K + (size_t)bh * S_ * HD_;
    const float* Vb = V + (size_t)bh * S_ * HD_;

    {
        int r = threadIdx.x >> 5;
        int c = (threadIdx.x & 31) * 4;
        float4 q4 = *(const float4*)&Qb[(size_t)(blockIdx.x * 8 + r) * HD_ + c];
        sQ[r][c + 0] = q4.x * scale;
        sQ[r][c + 1] = q4.y * scale;
        sQ[r][c + 2] = q4.z * scale;
        sQ[r][c + 3] = q4.w * scale;
    }

    float m = -INFINITY, l = 0.f;
    float4 acc = make_float4(0.f, 0.f, 0.f, 0.f);

    const int maxRow = blockIdx.x * 8 + 7;
    const int nTiles = maxRow / 32 + 1;

    for (int t = 0; t < nTiles; t++) {
        const int j0 = t * 32;
        {
            int r = threadIdx.x >> 3;
            int c = (threadIdx.x & 7) * 16;
#pragma unroll
            for (int i = 0; i < 16; i += 4) {
                *(float4*)&sK[r][c + i] = *(const float4*)&Kb[(size_t)(j0 + r) * HD_ + c + i];
                *(float4*)&sV[r][c + i] = *(const float4*)&Vb[(size_t)(j0 + r) * HD_ + c + i];
            }
        }
        __syncthreads();

        if (j0 <= qr) {
            const int j = j0 + lane;
            float s = -INFINITY;
            if (j <= qr) {
                s = 0.f;
#pragma unroll
                for (int d = 0; d < 128; d += 4) {
                    float4 q4 = *(const float4*)&sQ[warp][d];
                    float4 k4 = *(const float4*)&sK[lane][d];
                    s += q4.x * k4.x + q4.y * k4.y + q4.z * k4.z + q4.w * k4.w;
                }
            }
            float tmax = s;
#pragma unroll
            for (int o = 16; o; o >>= 1) tmax = fmaxf(tmax, __shfl_xor_sync(0xffffffffu, tmax, o));
            const float mn = fmaxf(m, tmax);
            const float p = (s == -INFINITY) ? 0.f : __expf(s - mn);
            const float corr = (m == -INFINITY) ? 0.f : __expf(m - mn);
            float psum = p;
#pragma unroll
            for (int o = 16; o; o >>= 1) psum += __shfl_xor_sync(0xffffffffu, psum, o);
            l = l * corr + psum;
            acc.x *= corr; acc.y *= corr; acc.z *= corr; acc.w *= corr;
#pragma unroll
            for (int jj = 0; jj < 32; jj++) {
                float pj = __shfl_sync(0xffffffffu, p, jj);
                float4 v4 = *(const float4*)&sV[jj][lane * 4];
                acc.x += pj * v4.x;
                acc.y += pj * v4.y;
                acc.z += pj * v4.z;
                acc.w += pj * v4.w;
            }
            m = mn;
        }
        __syncthreads();
    }

    const float inv = 1.f / l;
    float4 o4 = make_float4(acc.x * inv, acc.y * inv, acc.z * inv, acc.w * inv);
    *(float4*)&O[(size_t)(b * S_ + qr) * D_ + h * HD_ + lane * 4] = o4;
}

// ---------------------------------------------------------------------------
// Launcher
// ---------------------------------------------------------------------------
extern "C" void kernel_launch(void* const* d_in, const int* in_sizes, int n_in,
                              void* d_out, int out_size) {
    const float* hs   = (const float*)d_in[0];
    const float* cosT = (const float*)d_in[1];
    const float* sinT = (const float*)d_in[2];
    const float* wq   = (const float*)d_in[3];
    const float* wk   = (const float*)d_in[4];
    const float* wv   = (const float*)d_in[5];
    const float* wo   = (const float*)d_in[6];

    float* out  = (float*)d_out;
    float* kout = out + (size_t)PER_TENSOR;
    float* vout = out + (size_t)2 * PER_TENSOR;

    float* scratch = nullptr; float* qbuf = nullptr; float* obuf = nullptr;
    cudaGetSymbolAddress((void**)&scratch, g_scratch);
    cudaGetSymbolAddress((void**)&qbuf, g_q);
    cudaGetSymbolAddress((void**)&obuf, g_o);

    cudaFuncSetAttribute(gemm_tf32, cudaFuncAttributeMaxDynamicSharedMemorySize, GEMM_SMEM);

    dim3 gemmGrid(D_ / BN, M_ / BM);   // (16, 32)
    dim3 ropeGrid((B_ * S_ * H_ * (HD_ / 2) + 255) / 256);
    dim3 transGrid((PER_TENSOR / 4 + 255) / 256);
    dim3 attnGrid(S_ / 8, B_ * H_);

    // Q projection + rope
    gemm_tf32<<<gemmGrid, 256, GEMM_SMEM>>>(hs, wq, scratch, M_, D_, D_);
    rope_transpose<<<ropeGrid, 256>>>(scratch, cosT, sinT, qbuf);
    // K projection + rope
    gemm_tf32<<<gemmGrid, 256, GEMM_SMEM>>>(hs, wk, scratch, M_, D_, D_);
    rope_transpose<<<ropeGrid, 256>>>(scratch, cosT, sinT, kout);
    // V projection + transpose
    gemm_tf32<<<gemmGrid, 256, GEMM_SMEM>>>(hs, wv, scratch, M_, D_, D_);
    transpose_bshd<<<transGrid, 256>>>(scratch, vout);
    // attention
    flash_attn<<<attnGrid, 256>>>(qbuf, kout, vout, obuf);
    // output projection
    gemm_tf32<<<gemmGrid, 256, GEMM_SMEM>>>(obuf, wo, out, M_, D_, D_);
}

// round 4
// speedup vs baseline: 4.7977x; 3.4387x over previous
#include <cuda_runtime.h>
#include <cuda_bf16.h>
#include <math.h>
#include <cstdint>

// Problem constants
#define B_  2
#define S_  2048
#define D_  2048
#define H_  16
#define HD_ 128
#define M_  (B_ * S_)               // 4096
#define PER_TENSOR (B_ * S_ * D_)   // 8388608

// ---------------------------------------------------------------------------
// Scratch (device globals — no allocation allowed)
// ---------------------------------------------------------------------------
__device__ float g_scratch[PER_TENSOR];  // projection output (B*S, D)
__device__ float g_q[PER_TENSOR];        // Q after rope (rounded), (B,H,S,hd)
__device__ float g_o[PER_TENSOR];        // attention out, (B,S,D) layout
__device__ float g_hsT[PER_TENSOR];      // tf32-rounded GEMM A operand
__device__ float g_wT[D_ * D_];          // tf32-rounded weight
__device__ float g_vt[PER_TENSOR];       // V transposed: (B,H,hd,S)

// ---------------------------------------------------------------------------
// tf32 RN rounding pass
// ---------------------------------------------------------------------------
__global__ void round_tf32_k(const float4* __restrict__ in, float4* __restrict__ out, int n4) {
    int i = blockIdx.x * blockDim.x + threadIdx.x;
    if (i >= n4) return;
    float4 v = in[i];
    uint32_t a, b, c, d;
    asm("cvt.rn.tf32.f32 %0, %1;" : "=r"(a) : "f"(v.x));
    asm("cvt.rn.tf32.f32 %0, %1;" : "=r"(b) : "f"(v.y));
    asm("cvt.rn.tf32.f32 %0, %1;" : "=r"(c) : "f"(v.z));
    asm("cvt.rn.tf32.f32 %0, %1;" : "=r"(d) : "f"(v.w));
    out[i] = make_float4(__uint_as_float(a), __uint_as_float(b),
                         __uint_as_float(c), __uint_as_float(d));
}

// ---------------------------------------------------------------------------
// Shared mma helpers
// ---------------------------------------------------------------------------
#define LDMX4(r0, r1, r2, r3, addr)                                           \
    asm volatile("ldmatrix.sync.aligned.m8n8.x4.shared.b16 {%0,%1,%2,%3}, [%4];" \
                 : "=r"(r0), "=r"(r1), "=r"(r2), "=r"(r3) : "r"(addr))

#define MMA_TF32(d, a, b0v, b1v)                                              \
    asm volatile("mma.sync.aligned.m16n8k8.row.col.f32.tf32.tf32.f32 "        \
                 "{%0,%1,%2,%3}, {%4,%5,%6,%7}, {%8,%9}, {%0,%1,%2,%3};"      \
                 : "+f"(d[0]), "+f"(d[1]), "+f"(d[2]), "+f"(d[3])             \
                 : "r"(a[0]), "r"(a[1]), "r"(a[2]), "r"(a[3]),                \
                   "r"(b0v), "r"(b1v))

// ---------------------------------------------------------------------------
// tf32 mma.sync GEMM (inputs PRE-ROUNDED to tf32): C[m,n] = sum_k A[m,k]*W[n,k]
// Tile 128x128x32, 256 threads (8 warps, warp tile 64x32), 3-stage cp.async.
// ---------------------------------------------------------------------------
#define BM 128
#define BN 128
#define BK 32
#define NSTAGE 3
#define STAGE_FLOATS (2 * BM * BK)
#define GEMM_SMEM (NSTAGE * STAGE_FLOATS * 4)  // 98304 bytes

__global__ __launch_bounds__(256, 1)
void gemm_tf32(const float* __restrict__ A, const float* __restrict__ W,
               float* __restrict__ C, int M, int N, int K) {
    extern __shared__ float smem[];
    const uint32_t sbase = (uint32_t)__cvta_generic_to_shared(smem);

    const int tid = threadIdx.x;
    const int lane = tid & 31;
    const int warp = tid >> 5;
    const int wm = warp >> 2;
    const int wn = warp & 3;

    const int rowBase = blockIdx.y * BM;
    const int colBase = blockIdx.x * BN;

    const int ldRow = tid >> 1;
    const int ldC0 = (tid & 1) * 4;
    const float* Ag = A + (size_t)(rowBase + ldRow) * K;
    const float* Wg = W + (size_t)(colBase + ldRow) * K;

    const int KT = K / BK;

    auto load_stage = [&](int kt, int stg) {
        uint32_t sA = sbase + stg * (STAGE_FLOATS * 4);
        uint32_t sB = sA + BM * BK * 4;
        const float* ga = Ag + kt * BK + ldC0 * 4;
        const float* gb = Wg + kt * BK + ldC0 * 4;
#pragma unroll
        for (int c = 0; c < 4; c++) {
            int ch = ldC0 + c;
            uint32_t off = (uint32_t)(ldRow * 128 + ((ch ^ (ldRow & 7)) << 4));
            uint64_t gA = __cvta_generic_to_global(ga + c * 4);
            uint64_t gB = __cvta_generic_to_global(gb + c * 4);
            asm volatile("cp.async.cg.shared.global [%0], [%1], 16;" :: "r"(sA + off), "l"(gA));
            asm volatile("cp.async.cg.shared.global [%0], [%1], 16;" :: "r"(sB + off), "l"(gB));
        }
    };

    const int aRowLoc = (lane & 7) + (((lane >> 3) & 1) << 3);
    const int bRowLoc = lane & 7;
    const int bChunkAdd = lane >> 3;

    float acc[4][4][4];
#pragma unroll
    for (int i = 0; i < 4; i++)
#pragma unroll
        for (int j = 0; j < 4; j++)
#pragma unroll
            for (int r = 0; r < 4; r++) acc[i][j][r] = 0.f;

    load_stage(0, 0);
    asm volatile("cp.async.commit_group;" ::: "memory");
    load_stage(1, 1);
    asm volatile("cp.async.commit_group;" ::: "memory");

    for (int kt = 0; kt < KT; kt++) {
        asm volatile("cp.async.wait_group 1;" ::: "memory");
        __syncthreads();

        const int stg = kt % NSTAGE;
        const uint32_t sA = sbase + stg * (STAGE_FLOATS * 4);
        const uint32_t sB = sA + BM * BK * 4;

#pragma unroll
        for (int p = 0; p < 2; p++) {
            uint32_t b[4][4];
#pragma unroll
            for (int nt = 0; nt < 4; nt++) {
                int row = wn * 32 + nt * 8 + bRowLoc;
                int ch = p * 4 + bChunkAdd;
                uint32_t addr = sB + row * 128 + ((ch ^ (row & 7)) << 4);
                LDMX4(b[nt][0], b[nt][1], b[nt][2], b[nt][3], addr);
            }
#pragma unroll
            for (int kh = 0; kh < 2; kh++) {
                const int ks = p * 2 + kh;
                uint32_t a[4][4];
#pragma unroll
                for (int mt = 0; mt < 4; mt++) {
                    int row = wm * 64 + mt * 16 + aRowLoc;
                    int ch = ks * 2 + (lane >> 4);
                    uint32_t addr = sA + row * 128 + ((ch ^ (row & 7)) << 4);
                    LDMX4(a[mt][0], a[mt][1], a[mt][2], a[mt][3], addr);
                }
#pragma unroll
                for (int mt = 0; mt < 4; mt++)
#pragma unroll
                    for (int nt = 0; nt < 4; nt++)
                        MMA_TF32(acc[mt][nt], a[mt], b[nt][kh * 2], b[nt][kh * 2 + 1]);
            }
        }

        if (kt + 2 < KT) load_stage(kt + 2, (kt + 2) % NSTAGE);
        asm volatile("cp.async.commit_group;" ::: "memory");
    }

    const int erow = lane >> 2;
    const int ecol = (lane & 3) * 2;
#pragma unroll
    for (int mt = 0; mt < 4; mt++) {
#pragma unroll
        for (int nt = 0; nt < 4; nt++) {
            int r0 = rowBase + wm * 64 + mt * 16 + erow;
            int c0 = colBase + wn * 32 + nt * 8 + ecol;
            *(float2*)&C[(size_t)r0 * N + c0] = make_float2(acc[mt][nt][0], acc[mt][nt][1]);
            *(float2*)&C[(size_t)(r0 + 8) * N + c0] = make_float2(acc[mt][nt][2], acc[mt][nt][3]);
        }
    }
}

// ---------------------------------------------------------------------------
// RoPE + transpose: X (B*S, D) -> out (B,H,S,hd); optional tf32 rounding
// ---------------------------------------------------------------------------
__global__ void rope_transpose(const float* __restrict__ X,
                               const float* __restrict__ cosT,
                               const float* __restrict__ sinT,
                               float* __restrict__ out, int do_round) {
    int idx = blockIdx.x * blockDim.x + threadIdx.x;
    if (idx >= B_ * S_ * H_ * (HD_ / 2)) return;
    int dp = idx & 63;
    int h  = (idx >> 6) & 15;
    int s  = (idx >> 10) & (S_ - 1);
    int b  = idx >> 21;

    const float* xr = X + (size_t)(b * S_ + s) * D_ + h * HD_;
    float x1 = xr[2 * dp];
    float x2 = xr[2 * dp + 1];
    float c  = cosT[s * (HD_ / 2) + dp];
    float sn = sinT[s * (HD_ / 2) + dp];

    float y0 = x1 * c - x2 * sn;
    float y1 = x1 * sn + x2 * c;
    if (do_round) {
        uint32_t u0, u1;
        asm("cvt.rn.tf32.f32 %0, %1;" : "=r"(u0) : "f"(y0));
        asm("cvt.rn.tf32.f32 %0, %1;" : "=r"(u1) : "f"(y1));
        y0 = __uint_as_float(u0); y1 = __uint_as_float(u1);
    }
    float* orow = out + ((size_t)(b * H_ + h) * S_ + s) * HD_;
    orow[2 * dp]     = y0;
    orow[2 * dp + 1] = y1;
}

// ---------------------------------------------------------------------------
// Transpose (for V output): X (B*S, D) -> out (B,H,S,hd)
// ---------------------------------------------------------------------------
__global__ void transpose_bshd(const float* __restrict__ X, float* __restrict__ out) {
    int idx = blockIdx.x * blockDim.x + threadIdx.x;
    if (idx >= PER_TENSOR / 4) return;
    int c4 = idx & 31;
    int h  = (idx >> 5) & 15;
    int s  = (idx >> 9) & (S_ - 1);
    int b  = idx >> 20;
    float4 v = *(const float4*)&X[(size_t)(b * S_ + s) * D_ + h * HD_ + c4 * 4];
    *(float4*)&out[((size_t)(b * H_ + h) * S_ + s) * HD_ + c4 * 4] = v;
}

// ---------------------------------------------------------------------------
// Transpose V for attention: X (B,S,D) -> Vt (B,H,hd,S). Tiled 32x32.
// grid: (S/32, HD/32, B*H), block 256 (32x8)
// ---------------------------------------------------------------------------
__global__ void transpose_vt(const float* __restrict__ X, float* __restrict__ Vt) {
    __shared__ float tile[32][33];
    const int bhid = blockIdx.z;
    const int b = bhid >> 4, h = bhid & 15;
    const int s0 = blockIdx.x * 32, d0 = blockIdx.y * 32;
    const int tx = threadIdx.x & 31, ty = threadIdx.x >> 5;
#pragma unroll
    for (int i = 0; i < 4; i++)
        tile[ty + i * 8][tx] = X[(size_t)(b * S_ + s0 + ty + i * 8) * D_ + h * HD_ + d0 + tx];
    __syncthreads();
#pragma unroll
    for (int i = 0; i < 4; i++)
        Vt[((size_t)bhid * HD_ + d0 + ty + i * 8) * S_ + s0 + tx] = tile[tx][ty + i * 8];
}

// ---------------------------------------------------------------------------
// Tensor-core flash attention (causal), tf32 mma.
// Q: (B,H,S,hd) rounded; K: (B,H,S,hd); Vt: (B,H,hd,S); O: (B,S,D)
// CTA: 64 q-rows, 4 warps (16 rows each). KV tiles 64, double-buffered.
// ---------------------------------------------------------------------------
#define AQ_BYTES  32768                      // 64 x 512B
#define AK_BYTES  32768                      // 64 x 512B
#define AV_BYTES  32768                      // 128 x 256B
#define AP_STRIDE 272                        // 68 floats per row
#define ATTN_SMEM (AQ_BYTES + 2*AK_BYTES + 2*AV_BYTES + 64*AP_STRIDE)  // 181248

__global__ __launch_bounds__(128, 1)
void flash_attn_mma(const float* __restrict__ Q, const float* __restrict__ K,
                    const float* __restrict__ Vt, float* __restrict__ O) {
    extern __shared__ float asmem[];
    const uint32_t sb = (uint32_t)__cvta_generic_to_shared(asmem);
    const uint32_t sQ = sb;
    const uint32_t sK0 = sb + AQ_BYTES;
    const uint32_t sV0 = sb + AQ_BYTES + 2 * AK_BYTES;
    const uint32_t sP = sb + AQ_BYTES + 2 * AK_BYTES + 2 * AV_BYTES;

    const int bh = blockIdx.y;
    const int b = bh >> 4, h = bh & 15;
    const int qt = gridDim.x - 1 - blockIdx.x;   // heavy tiles first
    const int q0 = qt * 64;
    const int nT = qt + 1;

    const int tid = threadIdx.x;
    const int lane = tid & 31;
    const int warp = tid >> 5;

    const float* Qg = Q + ((size_t)bh * S_ + q0) * HD_;
    const float* Kg = K + (size_t)bh * S_ * HD_;
    const float* Vg = Vt + (size_t)bh * HD_ * S_;

    const int lr = tid >> 1;            // 0..63 (Q/K rows)
    const int lc0 = (tid & 1) * 16;     // chunk base

    // Q tile: 64 rows x 32 chunks
    {
#pragma unroll
        for (int c = 0; c < 16; c++) {
            int ch = lc0 + c;
            uint32_t off = (uint32_t)(lr * 512 + ((ch ^ (lr & 7)) << 4));
            uint64_t g = __cvta_generic_to_global(Qg + (size_t)lr * HD_ + ch * 4);
            asm volatile("cp.async.cg.shared.global [%0], [%1], 16;" :: "r"(sQ + off), "l"(g));
        }
    }

    auto loadKV = [&](int t) {
        const int j0 = t * 64;
        uint32_t kdst = sK0 + (t & 1) * AK_BYTES;
        uint32_t vdst = sV0 + (t & 1) * AV_BYTES;
#pragma unroll
        for (int c = 0; c < 16; c++) {
            int ch = lc0 + c;
            uint32_t off = (uint32_t)(lr * 512 + ((ch ^ (lr & 7)) << 4));
            uint64_t g = __cvta_generic_to_global(Kg + (size_t)(j0 + lr) * HD_ + ch * 4);
            asm volatile("cp.async.cg.shared.global [%0], [%1], 16;" :: "r"(kdst + off), "l"(g));
        }
#pragma unroll
        for (int c = 0; c < 16; c++) {
            uint32_t off = (uint32_t)(tid * 256 + ((c ^ (tid & 7)) << 4));
            uint64_t g = __cvta_generic_to_global(Vg + (size_t)tid * S_ + j0 + c * 4);
            asm volatile("cp.async.cg.shared.global [%0], [%1], 16;" :: "r"(vdst + off), "l"(g));
        }
    };

    loadKV(0);
    asm volatile("cp.async.commit_group;" ::: "memory");
    if (nT > 1) loadKV(1);
    asm volatile("cp.async.commit_group;" ::: "memory");

    const float scale = 0.08838834764831845f;   // 1/sqrt(128)
    float m0 = -INFINITY, m1 = -INFINITY, l0 = 0.f, l1 = 0.f;
    float o[16][4];
#pragma unroll
    for (int i = 0; i < 16; i++)
#pragma unroll
        for (int r = 0; r < 4; r++) o[i][r] = 0.f;

    const int aRowLoc = (lane & 7) + (((lane >> 3) & 1) << 3);
    const int rloc = lane >> 2;          // acc row within 8
    const int cloc = (lane & 3) * 2;     // acc col pair

    for (int t = 0; t < nT; t++) {
        asm volatile("cp.async.wait_group 1;" ::: "memory");
        __syncthreads();
        const uint32_t kb = sK0 + (t & 1) * AK_BYTES;
        const uint32_t vb = sV0 + (t & 1) * AV_BYTES;

        // ---- S = Q K^T (16 q rows per warp x 64 kv cols)
        float s[8][4];
#pragma unroll
        for (int nt = 0; nt < 8; nt++)
#pragma unroll
            for (int r = 0; r < 4; r++) s[nt][r] = 0.f;

#pragma unroll
        for (int p = 0; p < 8; p++) {
            uint32_t bk[8][4];
#pragma unroll
            for (int nt = 0; nt < 8; nt++) {
                int row = nt * 8 + (lane & 7);
                int ch = p * 4 + (lane >> 3);
                uint32_t addr = kb + row * 512 + ((ch ^ (row & 7)) << 4);
                LDMX4(bk[nt][0], bk[nt][1], bk[nt][2], bk[nt][3], addr);
            }
#pragma unroll
            for (int kh = 0; kh < 2; kh++) {
                const int ks = p * 2 + kh;
                uint32_t a[4];
                int row = warp * 16 + aRowLoc;
                int ch = ks * 2 + (lane >> 4);
                uint32_t addr = sQ + row * 512 + ((ch ^ (row & 7)) << 4);
                LDMX4(a[0], a[1], a[2], a[3], addr);
#pragma unroll
                for (int nt = 0; nt < 8; nt++)
                    MMA_TF32(s[nt], a, bk[nt][kh * 2], bk[nt][kh * 2 + 1]);
            }
        }

        // ---- softmax update
        const int r0g = q0 + warp * 16 + rloc;        // global q row (c0/c1)
        const bool diag = (t == nT - 1);
#pragma unroll
        for (int nt = 0; nt < 8; nt++) {
#pragma unroll
            for (int r = 0; r < 4; r++) s[nt][r] *= scale;
            if (diag) {
                int colg = t * 64 + nt * 8 + cloc;
                if (colg     > r0g)     s[nt][0] = -1e30f;
                if (colg + 1 > r0g)     s[nt][1] = -1e30f;
                if (colg     > r0g + 8) s[nt][2] = -1e30f;
                if (colg + 1 > r0g + 8) s[nt][3] = -1e30f;
            }
        }
        float vm0 = -1e30f, vm1 = -1e30f;
#pragma unroll
        for (int nt = 0; nt < 8; nt++) {
            vm0 = fmaxf(vm0, fmaxf(s[nt][0], s[nt][1]));
            vm1 = fmaxf(vm1, fmaxf(s[nt][2], s[nt][3]));
        }
        vm0 = fmaxf(vm0, __shfl_xor_sync(0xffffffffu, vm0, 1));
        vm0 = fmaxf(vm0, __shfl_xor_sync(0xffffffffu, vm0, 2));
        vm1 = fmaxf(vm1, __shfl_xor_sync(0xffffffffu, vm1, 1));
        vm1 = fmaxf(vm1, __shfl_xor_sync(0xffffffffu, vm1, 2));
        const float mn0 = fmaxf(m0, vm0), mn1 = fmaxf(m1, vm1);
        const float cr0 = __expf(m0 - mn0), cr1 = __expf(m1 - mn1);

        float ps0 = 0.f, ps1 = 0.f;
#pragma unroll
        for (int nt = 0; nt < 8; nt++) {
            s[nt][0] = __expf(s[nt][0] - mn0);
            s[nt][1] = __expf(s[nt][1] - mn0);
            s[nt][2] = __expf(s[nt][2] - mn1);
            s[nt][3] = __expf(s[nt][3] - mn1);
            ps0 += s[nt][0] + s[nt][1];
            ps1 += s[nt][2] + s[nt][3];
        }
        ps0 += __shfl_xor_sync(0xffffffffu, ps0, 1);
        ps0 += __shfl_xor_sync(0xffffffffu, ps0, 2);
        ps1 += __shfl_xor_sync(0xffffffffu, ps1, 1);
        ps1 += __shfl_xor_sync(0xffffffffu, ps1, 2);
        l0 = l0 * cr0 + ps0;
        l1 = l1 * cr1 + ps1;
        m0 = mn0; m1 = mn1;
#pragma unroll
        for (int i = 0; i < 16; i++) {
            o[i][0] *= cr0; o[i][1] *= cr0;
            o[i][2] *= cr1; o[i][3] *= cr1;
        }

        // ---- store P to smem (tf32-rounded), per-warp private rows
        {
            const int prow = warp * 16 + rloc;
#pragma unroll
            for (int nt = 0; nt < 8; nt++) {
                uint32_t u0, u1, u2, u3;
                asm("cvt.rn.tf32.f32 %0, %1;" : "=r"(u0) : "f"(s[nt][0]));
                asm("cvt.rn.tf32.f32 %0, %1;" : "=r"(u1) : "f"(s[nt][1]));
                asm("cvt.rn.tf32.f32 %0, %1;" : "=r"(u2) : "f"(s[nt][2]));
                asm("cvt.rn.tf32.f32 %0, %1;" : "=r"(u3) : "f"(s[nt][3]));
                uint32_t a0 = sP + prow * AP_STRIDE + (nt * 8 + cloc) * 4;
                uint32_t a1 = sP + (prow + 8) * AP_STRIDE + (nt * 8 + cloc) * 4;
                asm volatile("st.shared.v2.b32 [%0], {%1, %2};" :: "r"(a0), "r"(u0), "r"(u1) : "memory");
                asm volatile("st.shared.v2.b32 [%0], {%1, %2};" :: "r"(a1), "r"(u2), "r"(u3) : "memory");
            }
        }
        __syncwarp();

        // ---- O += P Vt  (k = 64 kv, n = 128 hd)
#pragma unroll
        for (int pp = 0; pp < 4; pp++) {
            uint32_t pa[2][4];
#pragma unroll
            for (int kh = 0; kh < 2; kh++) {
                int ks = pp * 2 + kh;
                int row = warp * 16 + aRowLoc;
                uint32_t addr = sP + row * AP_STRIDE + (ks * 2 + (lane >> 4)) * 16;
                LDMX4(pa[kh][0], pa[kh][1], pa[kh][2], pa[kh][3], addr);
            }
#pragma unroll
            for (int half = 0; half < 2; half++) {
                uint32_t bv[8][4];
#pragma unroll
                for (int i = 0; i < 8; i++) {
                    int row = (half * 8 + i) * 8 + (lane & 7);
                    int ch = pp * 4 + (lane >> 3);
                    uint32_t addr = vb + row * 256 + ((ch ^ (row & 7)) << 4);
                    LDMX4(bv[i][0], bv[i][1], bv[i][2], bv[i][3], addr);
                }
#pragma unroll
                for (int kh = 0; kh < 2; kh++)
#pragma unroll
                    for (int i = 0; i < 8; i++)
                        MMA_TF32(o[half * 8 + i], pa[kh], bv[i][kh * 2], bv[i][kh * 2 + 1]);
            }
        }

        __syncthreads();
        if (t + 2 < nT) loadKV(t + 2);
        asm volatile("cp.async.commit_group;" ::: "memory");
    }

    // ---- write O
    const float inv0 = 1.f / l0, inv1 = 1.f / l1;
    const int gr0 = q0 + warp * 16 + rloc;
#pragma unroll
    for (int nt = 0; nt < 16; nt++) {
        int col = h * HD_ + nt * 8 + cloc;
        *(float2*)&O[(size_t)(b * S_ + gr0) * D_ + col] =
            make_float2(o[nt][0] * inv0, o[nt][1] * inv0);
        *(float2*)&O[(size_t)(b * S_ + gr0 + 8) * D_ + col] =
            make_float2(o[nt][2] * inv1, o[nt][3] * inv1);
    }
}

// ---------------------------------------------------------------------------
// Launcher
// ---------------------------------------------------------------------------
extern "C" void kernel_launch(void* const* d_in, const int* in_sizes, int n_in,
                              void* d_out, int out_size) {
    const float* hs   = (const float*)d_in[0];
    const float* cosT = (const float*)d_in[1];
    const float* sinT = (const float*)d_in[2];
    const float* wq   = (const float*)d_in[3];
    const float* wk   = (const float*)d_in[4];
    const float* wv   = (const float*)d_in[5];
    const float* wo   = (const float*)d_in[6];

    float* out  = (float*)d_out;
    float* kout = out + (size_t)PER_TENSOR;
    float* vout = out + (size_t)2 * PER_TENSOR;

    float* scratch = nullptr; float* qbuf = nullptr; float* obuf = nullptr;
    float* hsT = nullptr; float* wT = nullptr; float* vt = nullptr;
    cudaGetSymbolAddress((void**)&scratch, g_scratch);
    cudaGetSymbolAddress((void**)&qbuf, g_q);
    cudaGetSymbolAddress((void**)&obuf, g_o);
    cudaGetSymbolAddress((void**)&hsT, g_hsT);
    cudaGetSymbolAddress((void**)&wT, g_wT);
    cudaGetSymbolAddress((void**)&vt, g_vt);

    cudaFuncSetAttribute(gemm_tf32, cudaFuncAttributeMaxDynamicSharedMemorySize, GEMM_SMEM);
    cudaFuncSetAttribute(flash_attn_mma, cudaFuncAttributeMaxDynamicSharedMemorySize, ATTN_SMEM);

    dim3 gemmGrid(D_ / BN, M_ / BM);
    dim3 ropeGrid((B_ * S_ * H_ * (HD_ / 2) + 255) / 256);
    dim3 transGrid((PER_TENSOR / 4 + 255) / 256);
    dim3 vtGrid(S_ / 32, HD_ / 32, B_ * H_);
    dim3 attnGrid(S_ / 64, B_ * H_);

    const int n4_hs = PER_TENSOR / 4;
    const int n4_w  = D_ * D_ / 4;

    round_tf32_k<<<(n4_hs + 255) / 256, 256>>>((const float4*)hs, (float4*)hsT, n4_hs);

    // Q projection + rope (rounded for attention)
    round_tf32_k<<<(n4_w + 255) / 256, 256>>>((const float4*)wq, (float4*)wT, n4_w);
    gemm_tf32<<<gemmGrid, 256, GEMM_SMEM>>>(hsT, wT, scratch, M_, D_, D_);
    rope_transpose<<<ropeGrid, 256>>>(scratch, cosT, sinT, qbuf, 1);

    // K projection + rope (exact — graded output)
    round_tf32_k<<<(n4_w + 255) / 256, 256>>>((const float4*)wk, (float4*)wT, n4_w);
    gemm_tf32<<<gemmGrid, 256, GEMM_SMEM>>>(hsT, wT, scratch, M_, D_, D_);
    rope_transpose<<<ropeGrid, 256>>>(scratch, cosT, sinT, kout, 0);

    // V projection: graded output + transposed attention operand
    round_tf32_k<<<(n4_w + 255) / 256, 256>>>((const float4*)wv, (float4*)wT, n4_w);
    gemm_tf32<<<gemmGrid, 256, GEMM_SMEM>>>(hsT, wT, scratch, M_, D_, D_);
    transpose_bshd<<<transGrid, 256>>>(scratch, vout);
    transpose_vt<<<vtGrid, 256>>>(scratch, vt);

    // attention
    flash_attn_mma<<<attnGrid, 128, ATTN_SMEM>>>(qbuf, kout, vt, obuf);

    // output projection
    round_tf32_k<<<(n4_hs + 255) / 256, 256>>>((const float4*)obuf, (float4*)hsT, n4_hs);
    round_tf32_k<<<(n4_w + 255) / 256, 256>>>((const float4*)wo, (float4*)wT, n4_w);
    gemm_tf32<<<gemmGrid, 256, GEMM_SMEM>>>(hsT, wT, out, M_, D_, D_);
}

// round 5
// speedup vs baseline: 9.8483x; 2.0527x over previous
#include <cuda_runtime.h>
#include <cuda_fp16.h>
#include <math.h>
#include <cstdint>

// Problem constants
#define B_  2
#define S_  2048
#define D_  2048
#define H_  16
#define HD_ 128
#define M_  (B_ * S_)               // 4096
#define PER_TENSOR (B_ * S_ * D_)   // 8388608

// ---------------------------------------------------------------------------
// Scratch (device globals — no allocation allowed)
// ---------------------------------------------------------------------------
__device__ float  g_scratch[PER_TENSOR];   // projection output (B*S, D) fp32
__device__ __half g_hs16[PER_TENSOR];      // hidden_states fp16
__device__ __half g_wq16[D_ * D_];
__device__ __half g_wk16[D_ * D_];
__device__ __half g_wv16[D_ * D_];
__device__ __half g_wo16[D_ * D_];
__device__ __half g_q16[PER_TENSOR];       // Q roped fp16 (B,H,S,hd)
__device__ __half g_k16[PER_TENSOR];       // K roped fp16 (B,H,S,hd)
__device__ __half g_v16[PER_TENSOR];       // V fp16 (B,H,S,hd)
__device__ __half g_o16[PER_TENSOR];       // attention out fp16 (B,S,D)

// ---------------------------------------------------------------------------
// fp32 -> fp16 conversion pass
// ---------------------------------------------------------------------------
__global__ void cvt_f16_k(const float4* __restrict__ in, __half2* __restrict__ out, int n4) {
    int i = blockIdx.x * blockDim.x + threadIdx.x;
    if (i >= n4) return;
    float4 v = in[i];
    __half2 h0 = __floats2half2_rn(v.x, v.y);
    __half2 h1 = __floats2half2_rn(v.z, v.w);
    uint2 pk = make_uint2(*(uint32_t*)&h0, *(uint32_t*)&h1);
    *(uint2*)&out[2 * i] = pk;
}

// ---------------------------------------------------------------------------
// mma helpers (fp16, fp32 accumulate)
// ---------------------------------------------------------------------------
#define LDMX4(r0, r1, r2, r3, addr)                                           \
    asm volatile("ldmatrix.sync.aligned.m8n8.x4.shared.b16 {%0,%1,%2,%3}, [%4];" \
                 : "=r"(r0), "=r"(r1), "=r"(r2), "=r"(r3) : "r"(addr))

#define LDMX4T(r0, r1, r2, r3, addr)                                          \
    asm volatile("ldmatrix.sync.aligned.m8n8.x4.trans.shared.b16 {%0,%1,%2,%3}, [%4];" \
                 : "=r"(r0), "=r"(r1), "=r"(r2), "=r"(r3) : "r"(addr))

#define MMA_F16(d, a, b0v, b1v)                                               \
    asm volatile("mma.sync.aligned.m16n8k16.row.col.f32.f16.f16.f32 "         \
                 "{%0,%1,%2,%3}, {%4,%5,%6,%7}, {%8,%9}, {%0,%1,%2,%3};"      \
                 : "+f"(d[0]), "+f"(d[1]), "+f"(d[2]), "+f"(d[3])             \
                 : "r"(a[0]), "r"(a[1]), "r"(a[2]), "r"(a[3]),                \
                   "r"(b0v), "r"(b1v))

// ---------------------------------------------------------------------------
// fp16 mma GEMM: C[m,n] = sum_k A[m,k] * W[n,k]  (fp32 out)
// A: (M x K) half row-major, W: (N x K) half row-major.
// Tile 128x128x64, 256 threads, warp tile 64x32, 3-stage cp.async, occ 2.
// ---------------------------------------------------------------------------
#define BM 128
#define BN 128
#define BK 64
#define NSTAGE 3
#define STAGE_BYTES (2 * BM * BK * 2)          // 32768
#define GEMM_SMEM (NSTAGE * STAGE_BYTES)       // 98304

__global__ __launch_bounds__(256, 2)
void gemm_f16(const __half* __restrict__ A, const __half* __restrict__ W,
              float* __restrict__ C, int M, int N, int K) {
    extern __shared__ char smem_raw[];
    const uint32_t sbase = (uint32_t)__cvta_generic_to_shared(smem_raw);

    const int tid = threadIdx.x;
    const int lane = tid & 31;
    const int warp = tid >> 5;
    const int wm = warp >> 2;        // 0..1
    const int wn = warp & 3;         // 0..3

    const int rowBase = blockIdx.y * BM;
    const int colBase = blockIdx.x * BN;

    const int ldRow = tid >> 1;              // 0..127
    const int ldC0 = (tid & 1) * 4;          // chunk 0..3 / 4..7
    const __half* Ag = A + (size_t)(rowBase + ldRow) * K;
    const __half* Wg = W + (size_t)(colBase + ldRow) * K;

    const int KT = K / BK;                   // 32

    auto load_stage = [&](int kt, int stg) {
        uint32_t sA = sbase + stg * STAGE_BYTES;
        uint32_t sB = sA + BM * BK * 2;
        const __half* ga = Ag + kt * BK + ldC0 * 8;
        const __half* gb = Wg + kt * BK + ldC0 * 8;
#pragma unroll
        for (int c = 0; c < 4; c++) {
            int ch = ldC0 + c;
            uint32_t off = (uint32_t)(ldRow * 128 + ((ch ^ (ldRow & 7)) << 4));
            uint64_t gA = __cvta_generic_to_global(ga + c * 8);
            uint64_t gB = __cvta_generic_to_global(gb + c * 8);
            asm volatile("cp.async.cg.shared.global [%0], [%1], 16;" :: "r"(sA + off), "l"(gA));
            asm volatile("cp.async.cg.shared.global [%0], [%1], 16;" :: "r"(sB + off), "l"(gB));
        }
    };

    float acc[4][4][4];
#pragma unroll
    for (int i = 0; i < 4; i++)
#pragma unroll
        for (int j = 0; j < 4; j++)
#pragma unroll
            for (int r = 0; r < 4; r++) acc[i][j][r] = 0.f;

    load_stage(0, 0);
    asm volatile("cp.async.commit_group;" ::: "memory");
    load_stage(1, 1);
    asm volatile("cp.async.commit_group;" ::: "memory");

    for (int kt = 0; kt < KT; kt++) {
        asm volatile("cp.async.wait_group 1;" ::: "memory");
        __syncthreads();

        const int stg = kt % NSTAGE;
        const uint32_t sA = sbase + stg * STAGE_BYTES;
        const uint32_t sB = sA + BM * BK * 2;

#pragma unroll
        for (int ks = 0; ks < 4; ks++) {     // k16 steps
            uint32_t a[4][4];
#pragma unroll
            for (int mt = 0; mt < 4; mt++) {
                int row = wm * 64 + mt * 16 + (lane & 15);
                int ch = ks * 2 + (lane >> 4);
                uint32_t addr = sA + row * 128 + ((ch ^ (row & 7)) << 4);
                LDMX4(a[mt][0], a[mt][1], a[mt][2], a[mt][3], addr);
            }
#pragma unroll
            for (int nb = 0; nb < 2; nb++) {
                uint32_t bf[4];
                int row = wn * 32 + nb * 16 + (lane & 7) + ((lane >> 4) & 1) * 8;
                int ch = ks * 2 + ((lane >> 3) & 1);
                uint32_t addr = sB + row * 128 + ((ch ^ (row & 7)) << 4);
                LDMX4(bf[0], bf[1], bf[2], bf[3], addr);
#pragma unroll
                for (int mt = 0; mt < 4; mt++) {
                    MMA_F16(acc[mt][nb * 2 + 0], a[mt], bf[0], bf[1]);
                    MMA_F16(acc[mt][nb * 2 + 1], a[mt], bf[2], bf[3]);
                }
            }
        }

        if (kt + 2 < KT) load_stage(kt + 2, (kt + 2) % NSTAGE);
        asm volatile("cp.async.commit_group;" ::: "memory");
    }

    const int erow = lane >> 2;
    const int ecol = (lane & 3) * 2;
#pragma unroll
    for (int mt = 0; mt < 4; mt++) {
#pragma unroll
        for (int n8 = 0; n8 < 4; n8++) {
            int r0 = rowBase + wm * 64 + mt * 16 + erow;
            int c0 = colBase + wn * 32 + n8 * 8 + ecol;
            *(float2*)&C[(size_t)r0 * N + c0] = make_float2(acc[mt][n8][0], acc[mt][n8][1]);
            *(float2*)&C[(size_t)(r0 + 8) * N + c0] = make_float2(acc[mt][n8][2], acc[mt][n8][3]);
        }
    }
}

// ---------------------------------------------------------------------------
// RoPE + transpose: X (B*S, D) -> fp16 (B,H,S,hd), optional fp32 copy
// ---------------------------------------------------------------------------
__global__ void rope_transpose(const float* __restrict__ X,
                               const float* __restrict__ cosT,
                               const float* __restrict__ sinT,
                               __half* __restrict__ out16,
                               float* __restrict__ out32) {
    int idx = blockIdx.x * blockDim.x + threadIdx.x;
    if (idx >= B_ * S_ * H_ * (HD_ / 2)) return;
    int dp = idx & 63;
    int h  = (idx >> 6) & 15;
    int s  = (idx >> 10) & (S_ - 1);
    int b  = idx >> 21;

    const float* xr = X + (size_t)(b * S_ + s) * D_ + h * HD_;
    float x1 = xr[2 * dp];
    float x2 = xr[2 * dp + 1];
    float c  = cosT[s * (HD_ / 2) + dp];
    float sn = sinT[s * (HD_ / 2) + dp];

    float y0 = x1 * c - x2 * sn;
    float y1 = x1 * sn + x2 * c;

    size_t ro = ((size_t)(b * H_ + h) * S_ + s) * HD_;
    ((__half2*)(out16 + ro))[dp] = __floats2half2_rn(y0, y1);
    if (out32) {
        out32[ro + 2 * dp]     = y0;
        out32[ro + 2 * dp + 1] = y1;
    }
}

// ---------------------------------------------------------------------------
// V transpose: X (B*S, D) -> fp32 (B,H,S,hd) graded output + fp16 copy
// ---------------------------------------------------------------------------
__global__ void transpose_bshd(const float* __restrict__ X,
                               float* __restrict__ out32,
                               __half* __restrict__ out16) {
    int idx = blockIdx.x * blockDim.x + threadIdx.x;
    if (idx >= PER_TENSOR / 4) return;
    int c4 = idx & 31;
    int h  = (idx >> 5) & 15;
    int s  = (idx >> 9) & (S_ - 1);
    int b  = idx >> 20;
    float4 v = *(const float4*)&X[(size_t)(b * S_ + s) * D_ + h * HD_ + c4 * 4];
    size_t o = ((size_t)(b * H_ + h) * S_ + s) * HD_ + c4 * 4;
    *(float4*)&out32[o] = v;
    __half2 h0 = __floats2half2_rn(v.x, v.y);
    __half2 h1 = __floats2half2_rn(v.z, v.w);
    *(uint2*)&out16[o] = make_uint2(*(uint32_t*)&h0, *(uint32_t*)&h1);
}

// ---------------------------------------------------------------------------
// fp16 tensor-core flash attention (causal).
// Q,K,V: (B,H,S,hd) fp16. O: (B,S,D) fp16 (A operand of the final GEMM).
// CTA: 64 q rows, 4 warps. KV tiles 64, double-buffered. occ 2.
// ---------------------------------------------------------------------------
#define AQ_B 16384                 // 64 x 256B
#define AK_B 16384
#define AV_B 16384
#define AP_B 8192                  // 64 x 128B
#define ATTN_SMEM (AQ_B + 2*AK_B + 2*AV_B + AP_B)   // 90112

__global__ __launch_bounds__(128, 2)
void flash_attn_f16(const __half* __restrict__ Q, const __half* __restrict__ K,
                    const __half* __restrict__ V, __half* __restrict__ O) {
    extern __shared__ char asmem[];
    const uint32_t sb = (uint32_t)__cvta_generic_to_shared(asmem);
    const uint32_t sQ = sb;
    const uint32_t sK0 = sb + AQ_B;
    const uint32_t sV0 = sb + AQ_B + 2 * AK_B;
    const uint32_t sP = sb + AQ_B + 2 * AK_B + 2 * AV_B;

    const int bh = blockIdx.y;
    const int b = bh >> 4, h = bh & 15;
    const int qt = gridDim.x - 1 - blockIdx.x;   // heavy tiles first
    const int q0 = qt * 64;
    const int nT = qt + 1;

    const int tid = threadIdx.x;
    const int lane = tid & 31;
    const int warp = tid >> 5;

    const __half* Qg = Q + ((size_t)bh * S_ + q0) * HD_;
    const __half* Kg = K + (size_t)bh * S_ * HD_;
    const __half* Vg = V + (size_t)bh * S_ * HD_;

    const int lr = tid >> 1;            // 0..63
    const int lc0 = (tid & 1) * 8;      // chunk base (16 chunks/row)

    // Q tile: 64 rows x 256B
#pragma unroll
    for (int c = 0; c < 8; c++) {
        int ch = lc0 + c;
        uint32_t off = (uint32_t)(lr * 256 + ((ch ^ (lr & 7)) << 4));
        uint64_t g = __cvta_generic_to_global(Qg + (size_t)lr * HD_ + ch * 8);
        asm volatile("cp.async.cg.shared.global [%0], [%1], 16;" :: "r"(sQ + off), "l"(g));
    }

    auto loadKV = [&](int t) {
        const int j0 = t * 64;
        uint32_t kdst = sK0 + (t & 1) * AK_B;
        uint32_t vdst = sV0 + (t & 1) * AV_B;
#pragma unroll
        for (int c = 0; c < 8; c++) {
            int ch = lc0 + c;
            uint32_t off = (uint32_t)(lr * 256 + ((ch ^ (lr & 7)) << 4));
            uint64_t gk = __cvta_generic_to_global(Kg + (size_t)(j0 + lr) * HD_ + ch * 8);
            uint64_t gv = __cvta_generic_to_global(Vg + (size_t)(j0 + lr) * HD_ + ch * 8);
            asm volatile("cp.async.cg.shared.global [%0], [%1], 16;" :: "r"(kdst + off), "l"(gk));
            asm volatile("cp.async.cg.shared.global [%0], [%1], 16;" :: "r"(vdst + off), "l"(gv));
        }
    };

    loadKV(0);
    asm volatile("cp.async.commit_group;" ::: "memory");
    if (nT > 1) loadKV(1);
    asm volatile("cp.async.commit_group;" ::: "memory");

    const float scale = 0.08838834764831845f;   // 1/sqrt(128)
    float m0 = -INFINITY, m1 = -INFINITY, l0 = 0.f, l1 = 0.f;
    float o[16][4];
#pragma unroll
    for (int i = 0; i < 16; i++)
#pragma unroll
        for (int r = 0; r < 4; r++) o[i][r] = 0.f;

    const int rloc = lane >> 2;
    const int cloc = (lane & 3) * 2;

    for (int t = 0; t < nT; t++) {
        asm volatile("cp.async.wait_group 1;" ::: "memory");
        __syncthreads();
        const uint32_t kb = sK0 + (t & 1) * AK_B;
        const uint32_t vb = sV0 + (t & 1) * AV_B;

        // ---- S = Q K^T (16 q rows x 64 kv cols per warp)
        float s[8][4];
#pragma unroll
        for (int nt = 0; nt < 8; nt++)
#pragma unroll
            for (int r = 0; r < 4; r++) s[nt][r] = 0.f;

#pragma unroll
        for (int ks = 0; ks < 8; ks++) {     // k = 128 hd = 8 x k16
            uint32_t a[4];
            {
                int row = warp * 16 + (lane & 15);
                int ch = ks * 2 + (lane >> 4);
                uint32_t addr = sQ + row * 256 + ((ch ^ (row & 7)) << 4);
                LDMX4(a[0], a[1], a[2], a[3], addr);
            }
#pragma unroll
            for (int nb = 0; nb < 4; nb++) {
                uint32_t bf[4];
                int row = nb * 16 + (lane & 7) + ((lane >> 4) & 1) * 8;
                int ch = ks * 2 + ((lane >> 3) & 1);
                uint32_t addr = kb + row * 256 + ((ch ^ (row & 7)) << 4);
                LDMX4(bf[0], bf[1], bf[2], bf[3], addr);
                MMA_F16(s[nb * 2 + 0], a, bf[0], bf[1]);
                MMA_F16(s[nb * 2 + 1], a, bf[2], bf[3]);
            }
        }

        // ---- softmax update
        const int r0g = q0 + warp * 16 + rloc;
        const bool diag = (t == nT - 1);
#pragma unroll
        for (int nt = 0; nt < 8; nt++) {
#pragma unroll
            for (int r = 0; r < 4; r++) s[nt][r] *= scale;
            if (diag) {
                int colg = t * 64 + nt * 8 + cloc;
                if (colg     > r0g)     s[nt][0] = -1e30f;
                if (colg + 1 > r0g)     s[nt][1] = -1e30f;
                if (colg     > r0g + 8) s[nt][2] = -1e30f;
                if (colg + 1 > r0g + 8) s[nt][3] = -1e30f;
            }
        }
        float vm0 = -1e30f, vm1 = -1e30f;
#pragma unroll
        for (int nt = 0; nt < 8; nt++) {
            vm0 = fmaxf(vm0, fmaxf(s[nt][0], s[nt][1]));
            vm1 = fmaxf(vm1, fmaxf(s[nt][2], s[nt][3]));
        }
        vm0 = fmaxf(vm0, __shfl_xor_sync(0xffffffffu, vm0, 1));
        vm0 = fmaxf(vm0, __shfl_xor_sync(0xffffffffu, vm0, 2));
        vm1 = fmaxf(vm1, __shfl_xor_sync(0xffffffffu, vm1, 1));
        vm1 = fmaxf(vm1, __shfl_xor_sync(0xffffffffu, vm1, 2));
        const float mn0 = fmaxf(m0, vm0), mn1 = fmaxf(m1, vm1);
        const float cr0 = __expf(m0 - mn0), cr1 = __expf(m1 - mn1);

        float ps0 = 0.f, ps1 = 0.f;
#pragma unroll
        for (int nt = 0; nt < 8; nt++) {
            s[nt][0] = __expf(s[nt][0] - mn0);
            s[nt][1] = __expf(s[nt][1] - mn0);
            s[nt][2] = __expf(s[nt][2] - mn1);
            s[nt][3] = __expf(s[nt][3] - mn1);
            ps0 += s[nt][0] + s[nt][1];
            ps1 += s[nt][2] + s[nt][3];
        }
        ps0 += __shfl_xor_sync(0xffffffffu, ps0, 1);
        ps0 += __shfl_xor_sync(0xffffffffu, ps0, 2);
        ps1 += __shfl_xor_sync(0xffffffffu, ps1, 1);
        ps1 += __shfl_xor_sync(0xffffffffu, ps1, 2);
        l0 = l0 * cr0 + ps0;
        l1 = l1 * cr1 + ps1;
        m0 = mn0; m1 = mn1;
#pragma unroll
        for (int i = 0; i < 16; i++) {
            o[i][0] *= cr0; o[i][1] *= cr0;
            o[i][2] *= cr1; o[i][3] *= cr1;
        }

        // ---- store P (fp16) to smem, per-warp private rows
        {
            const int prow = warp * 16 + rloc;
#pragma unroll
            for (int nt = 0; nt < 8; nt++) {
                __half2 h0 = __floats2half2_rn(s[nt][0], s[nt][1]);
                __half2 h1 = __floats2half2_rn(s[nt][2], s[nt][3]);
                int bytecol = (nt * 8 + cloc) * 2;
                int chk = bytecol >> 4, rem = bytecol & 15;
                uint32_t a0 = sP + prow * 128 + ((chk ^ (prow & 7)) << 4) + rem;
                int prow2 = prow + 8;
                uint32_t a1 = sP + prow2 * 128 + ((chk ^ (prow2 & 7)) << 4) + rem;
                asm volatile("st.shared.b32 [%0], %1;" :: "r"(a0), "r"(*(uint32_t*)&h0) : "memory");
                asm volatile("st.shared.b32 [%0], %1;" :: "r"(a1), "r"(*(uint32_t*)&h1) : "memory");
            }
        }
        __syncwarp();

        // ---- O += P V  (k = 64 kv, n = 128 hd), V via ldmatrix.trans
#pragma unroll
        for (int pp = 0; pp < 4; pp++) {     // k16 steps over kv
            uint32_t pa[4];
            {
                int row = warp * 16 + (lane & 15);
                int ch = pp * 2 + (lane >> 4);
                uint32_t addr = sP + row * 128 + ((ch ^ (row & 7)) << 4);
                LDMX4(pa[0], pa[1], pa[2], pa[3], addr);
            }
#pragma unroll
            for (int nb = 0; nb < 8; nb++) { // hd blocks of 16
                uint32_t bf[4];
                int row = pp * 16 + (lane & 7) + ((lane >> 3) & 1) * 8;   // kv row
                int ch = nb * 2 + ((lane >> 4) & 1);                       // hd chunk
                uint32_t addr = vb + row * 256 + ((ch ^ (row & 7)) << 4);
                LDMX4T(bf[0], bf[1], bf[2], bf[3], addr);
                MMA_F16(o[nb * 2 + 0], pa, bf[0], bf[1]);
                MMA_F16(o[nb * 2 + 1], pa, bf[2], bf[3]);
            }
        }

        __syncthreads();
        if (t + 2 < nT) loadKV(t + 2);
        asm volatile("cp.async.commit_group;" ::: "memory");
    }

    // ---- write O (fp16, (B,S,D) layout)
    const float inv0 = 1.f / l0, inv1 = 1.f / l1;
    const int gr0 = q0 + warp * 16 + rloc;
#pragma unroll
    for (int nt = 0; nt < 16; nt++) {
        int col = h * HD_ + nt * 8 + cloc;
        __half2 h0 = __floats2half2_rn(o[nt][0] * inv0, o[nt][1] * inv0);
        __half2 h1 = __floats2half2_rn(o[nt][2] * inv1, o[nt][3] * inv1);
        *(__half2*)&O[(size_t)(b * S_ + gr0) * D_ + col] = h0;
        *(__half2*)&O[(size_t)(b * S_ + gr0 + 8) * D_ + col] = h1;
    }
}

// ---------------------------------------------------------------------------
// Launcher
// ---------------------------------------------------------------------------
extern "C" void kernel_launch(void* const* d_in, const int* in_sizes, int n_in,
                              void* d_out, int out_size) {
    const float* hs   = (const float*)d_in[0];
    const float* cosT = (const float*)d_in[1];
    const float* sinT = (const float*)d_in[2];
    const float* wq   = (const float*)d_in[3];
    const float* wk   = (const float*)d_in[4];
    const float* wv   = (const float*)d_in[5];
    const float* wo   = (const float*)d_in[6];

    float* out  = (float*)d_out;
    float* kout = out + (size_t)PER_TENSOR;
    float* vout = out + (size_t)2 * PER_TENSOR;

    float* scratch = nullptr;
    __half *hs16, *wq16, *wk16, *wv16, *wo16, *q16, *k16, *v16, *o16;
    cudaGetSymbolAddress((void**)&scratch, g_scratch);
    cudaGetSymbolAddress((void**)&hs16, g_hs16);
    cudaGetSymbolAddress((void**)&wq16, g_wq16);
    cudaGetSymbolAddress((void**)&wk16, g_wk16);
    cudaGetSymbolAddress((void**)&wv16, g_wv16);
    cudaGetSymbolAddress((void**)&wo16, g_wo16);
    cudaGetSymbolAddress((void**)&q16, g_q16);
    cudaGetSymbolAddress((void**)&k16, g_k16);
    cudaGetSymbolAddress((void**)&v16, g_v16);
    cudaGetSymbolAddress((void**)&o16, g_o16);

    cudaFuncSetAttribute(gemm_f16, cudaFuncAttributeMaxDynamicSharedMemorySize, GEMM_SMEM);
    cudaFuncSetAttribute(flash_attn_f16, cudaFuncAttributeMaxDynamicSharedMemorySize, ATTN_SMEM);

    dim3 gemmGrid(D_ / BN, M_ / BM);   // (16, 32)
    dim3 ropeGrid((B_ * S_ * H_ * (HD_ / 2) + 255) / 256);
    dim3 transGrid((PER_TENSOR / 4 + 255) / 256);
    dim3 attnGrid(S_ / 64, B_ * H_);   // (32, 32)

    const int n4_hs = PER_TENSOR / 4;
    const int n4_w  = D_ * D_ / 4;

    // convert inputs to fp16
    cvt_f16_k<<<(n4_hs + 255) / 256, 256>>>((const float4*)hs, (__half2*)hs16, n4_hs);
    cvt_f16_k<<<(n4_w + 255) / 256, 256>>>((const float4*)wq, (__half2*)wq16, n4_w);
    cvt_f16_k<<<(n4_w + 255) / 256, 256>>>((const float4*)wk, (__half2*)wk16, n4_w);
    cvt_f16_k<<<(n4_w + 255) / 256, 256>>>((const float4*)wv, (__half2*)wv16, n4_w);
    cvt_f16_k<<<(n4_w + 255) / 256, 256>>>((const float4*)wo, (__half2*)wo16, n4_w);

    // Q projection + rope (fp16 only)
    gemm_f16<<<gemmGrid, 256, GEMM_SMEM>>>(hs16, wq16, scratch, M_, D_, D_);
    rope_transpose<<<ropeGrid, 256>>>(scratch, cosT, sinT, q16, nullptr);

    // K projection + rope (fp32 graded + fp16 attention operand)
    gemm_f16<<<gemmGrid, 256, GEMM_SMEM>>>(hs16, wk16, scratch, M_, D_, D_);
    rope_transpose<<<ropeGrid, 256>>>(scratch, cosT, sinT, k16, kout);

    // V projection (fp32 graded + fp16)
    gemm_f16<<<gemmGrid, 256, GEMM_SMEM>>>(hs16, wv16, scratch, M_, D_, D_);
    transpose_bshd<<<transGrid, 256>>>(scratch, vout, v16);

    // attention -> fp16 O (direct A operand of final GEMM)
    flash_attn_f16<<<attnGrid, 128, ATTN_SMEM>>>(q16, k16, v16, o16);

    // output projection (fp32 out)
    gemm_f16<<<gemmGrid, 256, GEMM_SMEM>>>(o16, wo16, out, M_, D_, D_);
}

// round 6
// speedup vs baseline: 10.1804x; 1.0337x over previous
#include <cuda_runtime.h>
#include <cuda_fp16.h>
#include <math.h>
#include <cstdint>

// Problem constants
#define B_  2
#define S_  2048
#define D_  2048
#define H_  16
#define HD_ 128
#define M_  (B_ * S_)               // 4096
#define PER_TENSOR (B_ * S_ * D_)   // 8388608

// ---------------------------------------------------------------------------
// Scratch (device globals — no allocation allowed)
// ---------------------------------------------------------------------------
__device__ __half g_hs16[PER_TENSOR];      // hidden_states fp16
__device__ __half g_wq16[D_ * D_];
__device__ __half g_wk16[D_ * D_];
__device__ __half g_wv16[D_ * D_];
__device__ __half g_wo16[D_ * D_];
__device__ __half g_q16[PER_TENSOR];       // Q roped fp16 (B,H,S,hd)
__device__ __half g_k16[PER_TENSOR];       // K roped fp16 (B,H,S,hd)
__device__ __half g_v16[PER_TENSOR];       // V fp16 (B,H,S,hd)
__device__ __half g_o16[PER_TENSOR];       // attention out fp16 (B,S,D)

// ---------------------------------------------------------------------------
// Segmented fp32 -> fp16 conversion (hs + 4 weights in one launch)
// ---------------------------------------------------------------------------
#define N4_HS (PER_TENSOR / 4)
#define N4_W  (D_ * D_ / 4)

__global__ void cvt_all_f16(const float4* __restrict__ hs,
                            const float4* __restrict__ wq,
                            const float4* __restrict__ wk,
                            const float4* __restrict__ wv,
                            const float4* __restrict__ wo,
                            __half2* __restrict__ hs16,
                            __half2* __restrict__ wq16,
                            __half2* __restrict__ wk16,
                            __half2* __restrict__ wv16,
                            __half2* __restrict__ wo16) {
    int i = blockIdx.x * blockDim.x + threadIdx.x;
    const float4* in; __half2* out; int idx;
    if (i < N4_HS) { in = hs; out = hs16; idx = i; }
    else {
        int j = i - N4_HS;
        int seg = j / N4_W; idx = j % N4_W;
        switch (seg) {
            case 0: in = wq; out = wq16; break;
            case 1: in = wk; out = wk16; break;
            case 2: in = wv; out = wv16; break;
            default: in = wo; out = wo16; break;
        }
    }
    float4 v = in[idx];
    __half2 h0 = __floats2half2_rn(v.x, v.y);
    __half2 h1 = __floats2half2_rn(v.z, v.w);
    *(uint2*)&out[2 * idx] = make_uint2(*(uint32_t*)&h0, *(uint32_t*)&h1);
}

// ---------------------------------------------------------------------------
// mma helpers (fp16, fp32 accumulate)
// ---------------------------------------------------------------------------
#define LDMX4(r0, r1, r2, r3, addr)                                           \
    asm volatile("ldmatrix.sync.aligned.m8n8.x4.shared.b16 {%0,%1,%2,%3}, [%4];" \
                 : "=r"(r0), "=r"(r1), "=r"(r2), "=r"(r3) : "r"(addr))

#define LDMX4T(r0, r1, r2, r3, addr)                                          \
    asm volatile("ldmatrix.sync.aligned.m8n8.x4.trans.shared.b16 {%0,%1,%2,%3}, [%4];" \
                 : "=r"(r0), "=r"(r1), "=r"(r2), "=r"(r3) : "r"(addr))

#define MMA_F16(d, a, b0v, b1v)                                               \
    asm volatile("mma.sync.aligned.m16n8k16.row.col.f32.f16.f16.f32 "         \
                 "{%0,%1,%2,%3}, {%4,%5,%6,%7}, {%8,%9}, {%0,%1,%2,%3};"      \
                 : "+f"(d[0]), "+f"(d[1]), "+f"(d[2]), "+f"(d[3])             \
                 : "r"(a[0]), "r"(a[1]), "r"(a[2]), "r"(a[3]),                \
                   "r"(b0v), "r"(b1v))

// ---------------------------------------------------------------------------
// fp16 mma GEMM with fused epilogue.
// MODE 0 (Q): rope -> fp16 (B,H,S,hd)
// MODE 1 (K): rope -> fp16 (B,H,S,hd) + fp32 (B,H,S,hd)
// MODE 2 (V): plain -> fp16 (B,H,S,hd) + fp32 (B,H,S,hd)
// MODE 3 (O): plain fp32 (B,S,D) row-major
// Tile 128x128x64, 256 threads, warp tile 64x32, 3-stage cp.async, occ 2.
// ---------------------------------------------------------------------------
#define BM 128
#define BN 128
#define BK 64
#define NSTAGE 3
#define STAGE_BYTES (2 * BM * BK * 2)          // 32768
#define GEMM_SMEM (NSTAGE * STAGE_BYTES)       // 98304

template <int MODE>
__global__ __launch_bounds__(256, 2)
void gemm_f16(const __half* __restrict__ A, const __half* __restrict__ W,
              float* __restrict__ C32, __half* __restrict__ C16,
              const float* __restrict__ cosT, const float* __restrict__ sinT) {
    extern __shared__ char smem_raw[];
    const uint32_t sbase = (uint32_t)__cvta_generic_to_shared(smem_raw);

    const int K = D_, N = D_;
    const int tid = threadIdx.x;
    const int lane = tid & 31;
    const int warp = tid >> 5;
    const int wm = warp >> 2;        // 0..1
    const int wn = warp & 3;         // 0..3

    const int rowBase = blockIdx.y * BM;
    const int colBase = blockIdx.x * BN;

    const int ldRow = tid >> 1;              // 0..127
    const int ldC0 = (tid & 1) * 4;          // chunk 0..3 / 4..7
    const __half* Ag = A + (size_t)(rowBase + ldRow) * K;
    const __half* Wg = W + (size_t)(colBase + ldRow) * K;

    const int KT = K / BK;                   // 32

    auto load_stage = [&](int kt, int stg) {
        uint32_t sA = sbase + stg * STAGE_BYTES;
        uint32_t sB = sA + BM * BK * 2;
        const __half* ga = Ag + kt * BK + ldC0 * 8;
        const __half* gb = Wg + kt * BK + ldC0 * 8;
#pragma unroll
        for (int c = 0; c < 4; c++) {
            int ch = ldC0 + c;
            uint32_t off = (uint32_t)(ldRow * 128 + ((ch ^ (ldRow & 7)) << 4));
            uint64_t gA = __cvta_generic_to_global(ga + c * 8);
            uint64_t gB = __cvta_generic_to_global(gb + c * 8);
            asm volatile("cp.async.cg.shared.global [%0], [%1], 16;" :: "r"(sA + off), "l"(gA));
            asm volatile("cp.async.cg.shared.global [%0], [%1], 16;" :: "r"(sB + off), "l"(gB));
        }
    };

    float acc[4][4][4];
#pragma unroll
    for (int i = 0; i < 4; i++)
#pragma unroll
        for (int j = 0; j < 4; j++)
#pragma unroll
            for (int r = 0; r < 4; r++) acc[i][j][r] = 0.f;

    load_stage(0, 0);
    asm volatile("cp.async.commit_group;" ::: "memory");
    load_stage(1, 1);
    asm volatile("cp.async.commit_group;" ::: "memory");

    for (int kt = 0; kt < KT; kt++) {
        asm volatile("cp.async.wait_group 1;" ::: "memory");
        __syncthreads();

        const int stg = kt % NSTAGE;
        const uint32_t sA = sbase + stg * STAGE_BYTES;
        const uint32_t sB = sA + BM * BK * 2;

#pragma unroll
        for (int ks = 0; ks < 4; ks++) {
            uint32_t a[4][4];
#pragma unroll
            for (int mt = 0; mt < 4; mt++) {
                int row = wm * 64 + mt * 16 + (lane & 15);
                int ch = ks * 2 + (lane >> 4);
                uint32_t addr = sA + row * 128 + ((ch ^ (row & 7)) << 4);
                LDMX4(a[mt][0], a[mt][1], a[mt][2], a[mt][3], addr);
            }
#pragma unroll
            for (int nb = 0; nb < 2; nb++) {
                uint32_t bf[4];
                int row = wn * 32 + nb * 16 + (lane & 7) + ((lane >> 4) & 1) * 8;
                int ch = ks * 2 + ((lane >> 3) & 1);
                uint32_t addr = sB + row * 128 + ((ch ^ (row & 7)) << 4);
                LDMX4(bf[0], bf[1], bf[2], bf[3], addr);
#pragma unroll
                for (int mt = 0; mt < 4; mt++) {
                    MMA_F16(acc[mt][nb * 2 + 0], a[mt], bf[0], bf[1]);
                    MMA_F16(acc[mt][nb * 2 + 1], a[mt], bf[2], bf[3]);
                }
            }
        }

        if (kt + 2 < KT) load_stage(kt + 2, (kt + 2) % NSTAGE);
        asm volatile("cp.async.commit_group;" ::: "memory");
    }

    // ------------- fused epilogue -------------
    const int erow = lane >> 2;
    const int ecol = (lane & 3) * 2;

#pragma unroll
    for (int mt = 0; mt < 4; mt++) {
#pragma unroll
        for (int n8 = 0; n8 < 4; n8++) {
            const int r0 = rowBase + wm * 64 + mt * 16 + erow;
            const int c0 = colBase + wn * 32 + n8 * 8 + ecol;
            float v[4] = {acc[mt][n8][0], acc[mt][n8][1], acc[mt][n8][2], acc[mt][n8][3]};

            if (MODE == 3) {
                *(float2*)&C32[(size_t)r0 * N + c0] = make_float2(v[0], v[1]);
                *(float2*)&C32[(size_t)(r0 + 8) * N + c0] = make_float2(v[2], v[3]);
            } else {
                const int h = c0 >> 7;          // head
                const int d = c0 & 127;         // dim within head (even)
                const int dp = d >> 1;
#pragma unroll
                for (int rr = 0; rr < 2; rr++) {
                    const int r = r0 + rr * 8;
                    const int b = r >> 11;
                    const int s = r & (S_ - 1);
                    float y0 = v[rr * 2], y1 = v[rr * 2 + 1];
                    if (MODE == 0 || MODE == 1) {
                        float c  = __ldg(&cosT[s * (HD_ / 2) + dp]);
                        float sn = __ldg(&sinT[s * (HD_ / 2) + dp]);
                        float t0 = y0 * c - y1 * sn;
                        float t1 = y0 * sn + y1 * c;
                        y0 = t0; y1 = t1;
                    }
                    const size_t off = ((size_t)(b * H_ + h) * S_ + s) * HD_ + d;
                    *(__half2*)&C16[off] = __floats2half2_rn(y0, y1);
                    if (MODE == 1 || MODE == 2)
                        *(float2*)&C32[off] = make_float2(y0, y1);
                }
            }
        }
    }
}

// ---------------------------------------------------------------------------
// fp16 tensor-core flash attention (causal).
// Q,K,V: (B,H,S,hd) fp16. O: (B,S,D) fp16 (A operand of the final GEMM).
// CTA: 64 q rows, 4 warps. KV tiles 64, double-buffered. occ 2.
// ---------------------------------------------------------------------------
#define AQ_B 16384                 // 64 x 256B
#define AK_B 16384
#define AV_B 16384
#define AP_B 8192                  // 64 x 128B
#define ATTN_SMEM (AQ_B + 2*AK_B + 2*AV_B + AP_B)   // 90112

__global__ __launch_bounds__(128, 2)
void flash_attn_f16(const __half* __restrict__ Q, const __half* __restrict__ K,
                    const __half* __restrict__ V, __half* __restrict__ O) {
    extern __shared__ char asmem[];
    const uint32_t sb = (uint32_t)__cvta_generic_to_shared(asmem);
    const uint32_t sQ = sb;
    const uint32_t sK0 = sb + AQ_B;
    const uint32_t sV0 = sb + AQ_B + 2 * AK_B;
    const uint32_t sP = sb + AQ_B + 2 * AK_B + 2 * AV_B;

    const int bh = blockIdx.y;
    const int b = bh >> 4, h = bh & 15;
    const int qt = gridDim.x - 1 - blockIdx.x;   // heavy tiles first
    const int q0 = qt * 64;
    const int nT = qt + 1;

    const int tid = threadIdx.x;
    const int lane = tid & 31;
    const int warp = tid >> 5;

    const __half* Qg = Q + ((size_t)bh * S_ + q0) * HD_;
    const __half* Kg = K + (size_t)bh * S_ * HD_;
    const __half* Vg = V + (size_t)bh * S_ * HD_;

    const int lr = tid >> 1;            // 0..63
    const int lc0 = (tid & 1) * 8;      // chunk base

#pragma unroll
    for (int c = 0; c < 8; c++) {
        int ch = lc0 + c;
        uint32_t off = (uint32_t)(lr * 256 + ((ch ^ (lr & 7)) << 4));
        uint64_t g = __cvta_generic_to_global(Qg + (size_t)lr * HD_ + ch * 8);
        asm volatile("cp.async.cg.shared.global [%0], [%1], 16;" :: "r"(sQ + off), "l"(g));
    }

    auto loadKV = [&](int t) {
        const int j0 = t * 64;
        uint32_t kdst = sK0 + (t & 1) * AK_B;
        uint32_t vdst = sV0 + (t & 1) * AV_B;
#pragma unroll
        for (int c = 0; c < 8; c++) {
            int ch = lc0 + c;
            uint32_t off = (uint32_t)(lr * 256 + ((ch ^ (lr & 7)) << 4));
            uint64_t gk = __cvta_generic_to_global(Kg + (size_t)(j0 + lr) * HD_ + ch * 8);
            uint64_t gv = __cvta_generic_to_global(Vg + (size_t)(j0 + lr) * HD_ + ch * 8);
            asm volatile("cp.async.cg.shared.global [%0], [%1], 16;" :: "r"(kdst + off), "l"(gk));
            asm volatile("cp.async.cg.shared.global [%0], [%1], 16;" :: "r"(vdst + off), "l"(gv));
        }
    };

    loadKV(0);
    asm volatile("cp.async.commit_group;" ::: "memory");
    if (nT > 1) loadKV(1);
    asm volatile("cp.async.commit_group;" ::: "memory");

    const float scale = 0.08838834764831845f;   // 1/sqrt(128)
    float m0 = -INFINITY, m1 = -INFINITY, l0 = 0.f, l1 = 0.f;
    float o[16][4];
#pragma unroll
    for (int i = 0; i < 16; i++)
#pragma unroll
        for (int r = 0; r < 4; r++) o[i][r] = 0.f;

    const int rloc = lane >> 2;
    const int cloc = (lane & 3) * 2;

    for (int t = 0; t < nT; t++) {
        asm volatile("cp.async.wait_group 1;" ::: "memory");
        __syncthreads();
        const uint32_t kb = sK0 + (t & 1) * AK_B;
        const uint32_t vb = sV0 + (t & 1) * AV_B;

        // ---- S = Q K^T
        float s[8][4];
#pragma unroll
        for (int nt = 0; nt < 8; nt++)
#pragma unroll
            for (int r = 0; r < 4; r++) s[nt][r] = 0.f;

#pragma unroll
        for (int ks = 0; ks < 8; ks++) {
            uint32_t a[4];
            {
                int row = warp * 16 + (lane & 15);
                int ch = ks * 2 + (lane >> 4);
                uint32_t addr = sQ + row * 256 + ((ch ^ (row & 7)) << 4);
                LDMX4(a[0], a[1], a[2], a[3], addr);
            }
#pragma unroll
            for (int nb = 0; nb < 4; nb++) {
                uint32_t bf[4];
                int row = nb * 16 + (lane & 7) + ((lane >> 4) & 1) * 8;
                int ch = ks * 2 + ((lane >> 3) & 1);
                uint32_t addr = kb + row * 256 + ((ch ^ (row & 7)) << 4);
                LDMX4(bf[0], bf[1], bf[2], bf[3], addr);
                MMA_F16(s[nb * 2 + 0], a, bf[0], bf[1]);
                MMA_F16(s[nb * 2 + 1], a, bf[2], bf[3]);
            }
        }

        // ---- softmax update
        const int r0g = q0 + warp * 16 + rloc;
        const bool diag = (t == nT - 1);
#pragma unroll
        for (int nt = 0; nt < 8; nt++) {
#pragma unroll
            for (int r = 0; r < 4; r++) s[nt][r] *= scale;
            if (diag) {
                int colg = t * 64 + nt * 8 + cloc;
                if (colg     > r0g)     s[nt][0] = -1e30f;
                if (colg + 1 > r0g)     s[nt][1] = -1e30f;
                if (colg     > r0g + 8) s[nt][2] = -1e30f;
                if (colg + 1 > r0g + 8) s[nt][3] = -1e30f;
            }
        }
        float vm0 = -1e30f, vm1 = -1e30f;
#pragma unroll
        for (int nt = 0; nt < 8; nt++) {
            vm0 = fmaxf(vm0, fmaxf(s[nt][0], s[nt][1]));
            vm1 = fmaxf(vm1, fmaxf(s[nt][2], s[nt][3]));
        }
        vm0 = fmaxf(vm0, __shfl_xor_sync(0xffffffffu, vm0, 1));
        vm0 = fmaxf(vm0, __shfl_xor_sync(0xffffffffu, vm0, 2));
        vm1 = fmaxf(vm1, __shfl_xor_sync(0xffffffffu, vm1, 1));
        vm1 = fmaxf(vm1, __shfl_xor_sync(0xffffffffu, vm1, 2));
        const float mn0 = fmaxf(m0, vm0), mn1 = fmaxf(m1, vm1);
        const float cr0 = __expf(m0 - mn0), cr1 = __expf(m1 - mn1);

        float ps0 = 0.f, ps1 = 0.f;
#pragma unroll
        for (int nt = 0; nt < 8; nt++) {
            s[nt][0] = __expf(s[nt][0] - mn0);
            s[nt][1] = __expf(s[nt][1] - mn0);
            s[nt][2] = __expf(s[nt][2] - mn1);
            s[nt][3] = __expf(s[nt][3] - mn1);
            ps0 += s[nt][0] + s[nt][1];
            ps1 += s[nt][2] + s[nt][3];
        }
        ps0 += __shfl_xor_sync(0xffffffffu, ps0, 1);
        ps0 += __shfl_xor_sync(0xffffffffu, ps0, 2);
        ps1 += __shfl_xor_sync(0xffffffffu, ps1, 1);
        ps1 += __shfl_xor_sync(0xffffffffu, ps1, 2);
        l0 = l0 * cr0 + ps0;
        l1 = l1 * cr1 + ps1;
        m0 = mn0; m1 = mn1;
#pragma unroll
        for (int i = 0; i < 16; i++) {
            o[i][0] *= cr0; o[i][1] *= cr0;
            o[i][2] *= cr1; o[i][3] *= cr1;
        }

        // ---- store P (fp16) to smem
        {
            const int prow = warp * 16 + rloc;
#pragma unroll
            for (int nt = 0; nt < 8; nt++) {
                __half2 h0 = __floats2half2_rn(s[nt][0], s[nt][1]);
                __half2 h1 = __floats2half2_rn(s[nt][2], s[nt][3]);
                int bytecol = (nt * 8 + cloc) * 2;
                int chk = bytecol >> 4, rem = bytecol & 15;
                uint32_t a0 = sP + prow * 128 + ((chk ^ (prow & 7)) << 4) + rem;
                int prow2 = prow + 8;
                uint32_t a1 = sP + prow2 * 128 + ((chk ^ (prow2 & 7)) << 4) + rem;
                asm volatile("st.shared.b32 [%0], %1;" :: "r"(a0), "r"(*(uint32_t*)&h0) : "memory");
                asm volatile("st.shared.b32 [%0], %1;" :: "r"(a1), "r"(*(uint32_t*)&h1) : "memory");
            }
        }
        __syncwarp();

        // ---- O += P V (V via ldmatrix.trans)
#pragma unroll
        for (int pp = 0; pp < 4; pp++) {
            uint32_t pa[4];
            {
                int row = warp * 16 + (lane & 15);
                int ch = pp * 2 + (lane >> 4);
                uint32_t addr = sP + row * 128 + ((ch ^ (row & 7)) << 4);
                LDMX4(pa[0], pa[1], pa[2], pa[3], addr);
            }
#pragma unroll
            for (int nb = 0; nb < 8; nb++) {
                uint32_t bf[4];
                int row = pp * 16 + (lane & 7) + ((lane >> 3) & 1) * 8;
                int ch = nb * 2 + ((lane >> 4) & 1);
                uint32_t addr = vb + row * 256 + ((ch ^ (row & 7)) << 4);
                LDMX4T(bf[0], bf[1], bf[2], bf[3], addr);
                MMA_F16(o[nb * 2 + 0], pa, bf[0], bf[1]);
                MMA_F16(o[nb * 2 + 1], pa, bf[2], bf[3]);
            }
        }

        __syncthreads();
        if (t + 2 < nT) loadKV(t + 2);
        asm volatile("cp.async.commit_group;" ::: "memory");
    }

    // ---- write O (fp16, (B,S,D))
    const float inv0 = 1.f / l0, inv1 = 1.f / l1;
    const int gr0 = q0 + warp * 16 + rloc;
#pragma unroll
    for (int nt = 0; nt < 16; nt++) {
        int col = h * HD_ + nt * 8 + cloc;
        *(__half2*)&O[(size_t)(b * S_ + gr0) * D_ + col] =
            __floats2half2_rn(o[nt][0] * inv0, o[nt][1] * inv0);
        *(__half2*)&O[(size_t)(b * S_ + gr0 + 8) * D_ + col] =
            __floats2half2_rn(o[nt][2] * inv1, o[nt][3] * inv1);
    }
}

// ---------------------------------------------------------------------------
// Launcher
// ---------------------------------------------------------------------------
extern "C" void kernel_launch(void* const* d_in, const int* in_sizes, int n_in,
                              void* d_out, int out_size) {
    const float* hs   = (const float*)d_in[0];
    const float* cosT = (const float*)d_in[1];
    const float* sinT = (const float*)d_in[2];
    const float* wq   = (const float*)d_in[3];
    const float* wk   = (const float*)d_in[4];
    const float* wv   = (const float*)d_in[5];
    const float* wo   = (const float*)d_in[6];

    float* out  = (float*)d_out;
    float* kout = out + (size_t)PER_TENSOR;
    float* vout = out + (size_t)2 * PER_TENSOR;

    __half *hs16, *wq16, *wk16, *wv16, *wo16, *q16, *k16, *v16, *o16;
    cudaGetSymbolAddress((void**)&hs16, g_hs16);
    cudaGetSymbolAddress((void**)&wq16, g_wq16);
    cudaGetSymbolAddress((void**)&wk16, g_wk16);
    cudaGetSymbolAddress((void**)&wv16, g_wv16);
    cudaGetSymbolAddress((void**)&wo16, g_wo16);
    cudaGetSymbolAddress((void**)&q16, g_q16);
    cudaGetSymbolAddress((void**)&k16, g_k16);
    cudaGetSymbolAddress((void**)&v16, g_v16);
    cudaGetSymbolAddress((void**)&o16, g_o16);

    cudaFuncSetAttribute(gemm_f16<0>, cudaFuncAttributeMaxDynamicSharedMemorySize, GEMM_SMEM);
    cudaFuncSetAttribute(gemm_f16<1>, cudaFuncAttributeMaxDynamicSharedMemorySize, GEMM_SMEM);
    cudaFuncSetAttribute(gemm_f16<2>, cudaFuncAttributeMaxDynamicSharedMemorySize, GEMM_SMEM);
    cudaFuncSetAttribute(gemm_f16<3>, cudaFuncAttributeMaxDynamicSharedMemorySize, GEMM_SMEM);
    cudaFuncSetAttribute(flash_attn_f16, cudaFuncAttributeMaxDynamicSharedMemorySize, ATTN_SMEM);

    dim3 gemmGrid(D_ / BN, M_ / BM);   // (16, 32)
    dim3 attnGrid(S_ / 64, B_ * H_);   // (32, 32)

    const int cvtN = N4_HS + 4 * N4_W;
    cvt_all_f16<<<(cvtN + 255) / 256, 256>>>(
        (const float4*)hs, (const float4*)wq, (const float4*)wk,
        (const float4*)wv, (const float4*)wo,
        (__half2*)hs16, (__half2*)wq16, (__half2*)wk16,
        (__half2*)wv16, (__half2*)wo16);

    // Q projection + fused rope -> fp16
    gemm_f16<0><<<gemmGrid, 256, GEMM_SMEM>>>(hs16, wq16, nullptr, q16, cosT, sinT);
    // K projection + fused rope -> fp16 + fp32 graded
    gemm_f16<1><<<gemmGrid, 256, GEMM_SMEM>>>(hs16, wk16, kout, k16, cosT, sinT);
    // V projection -> fp16 + fp32 graded
    gemm_f16<2><<<gemmGrid, 256, GEMM_SMEM>>>(hs16, wv16, vout, v16, nullptr, nullptr);
    // attention -> fp16 O
    flash_attn_f16<<<attnGrid, 128, ATTN_SMEM>>>(q16, k16, v16, o16);
    // output projection -> fp32
    gemm_f16<3><<<gemmGrid, 256, GEMM_SMEM>>>(o16, wo16, out, nullptr, nullptr, nullptr);
}

// round 7
// speedup vs baseline: 11.2392x; 1.1040x over previous
#include <cuda_runtime.h>
#include <cuda_fp16.h>
#include <math.h>
#include <cstdint>

// Problem constants
#define B_  2
#define S_  2048
#define D_  2048
#define H_  16
#define HD_ 128
#define M_  (B_ * S_)               // 4096
#define PER_TENSOR (B_ * S_ * D_)   // 8388608

// ---------------------------------------------------------------------------
// Scratch (device globals — no allocation allowed)
// ---------------------------------------------------------------------------
__device__ __half g_hs16[PER_TENSOR];      // hidden_states fp16
__device__ __half g_wq16[D_ * D_];
__device__ __half g_wk16[D_ * D_];
__device__ __half g_wv16[D_ * D_];
__device__ __half g_wo16[D_ * D_];
__device__ __half g_q16[PER_TENSOR];       // Q roped fp16 (B,H,S,hd)
__device__ __half g_k16[PER_TENSOR];       // K roped fp16 (B,H,S,hd)
__device__ __half g_v16[PER_TENSOR];       // V fp16 (B,H,S,hd)
__device__ __half g_o16[PER_TENSOR];       // attention out fp16 (B,S,D)

// ---------------------------------------------------------------------------
// Segmented fp32 -> fp16 conversion (hs + 4 weights in one launch)
// ---------------------------------------------------------------------------
#define N4_HS (PER_TENSOR / 4)
#define N4_W  (D_ * D_ / 4)

__global__ void cvt_all_f16(const float4* __restrict__ hs,
                            const float4* __restrict__ wq,
                            const float4* __restrict__ wk,
                            const float4* __restrict__ wv,
                            const float4* __restrict__ wo,
                            __half2* __restrict__ hs16,
                            __half2* __restrict__ wq16,
                            __half2* __restrict__ wk16,
                            __half2* __restrict__ wv16,
                            __half2* __restrict__ wo16) {
    int i = blockIdx.x * blockDim.x + threadIdx.x;
    const float4* in; __half2* out; int idx;
    if (i < N4_HS) { in = hs; out = hs16; idx = i; }
    else {
        int j = i - N4_HS;
        int seg = j / N4_W; idx = j % N4_W;
        switch (seg) {
            case 0: in = wq; out = wq16; break;
            case 1: in = wk; out = wk16; break;
            case 2: in = wv; out = wv16; break;
            default: in = wo; out = wo16; break;
        }
    }
    float4 v = in[idx];
    __half2 h0 = __floats2half2_rn(v.x, v.y);
    __half2 h1 = __floats2half2_rn(v.z, v.w);
    *(uint2*)&out[2 * idx] = make_uint2(*(uint32_t*)&h0, *(uint32_t*)&h1);
}

// ---------------------------------------------------------------------------
// mma helpers (fp16, fp32 accumulate)
// ---------------------------------------------------------------------------
#define LDMX4(r0, r1, r2, r3, addr)                                           \
    asm volatile("ldmatrix.sync.aligned.m8n8.x4.shared.b16 {%0,%1,%2,%3}, [%4];" \
                 : "=r"(r0), "=r"(r1), "=r"(r2), "=r"(r3) : "r"(addr))

#define LDMX4T(r0, r1, r2, r3, addr)                                          \
    asm volatile("ldmatrix.sync.aligned.m8n8.x4.trans.shared.b16 {%0,%1,%2,%3}, [%4];" \
                 : "=r"(r0), "=r"(r1), "=r"(r2), "=r"(r3) : "r"(addr))

#define MMA_F16(d, a, b0v, b1v)                                               \
    asm volatile("mma.sync.aligned.m16n8k16.row.col.f32.f16.f16.f32 "         \
                 "{%0,%1,%2,%3}, {%4,%5,%6,%7}, {%8,%9}, {%0,%1,%2,%3};"      \
                 : "+f"(d[0]), "+f"(d[1]), "+f"(d[2]), "+f"(d[3])             \
                 : "r"(a[0]), "r"(a[1]), "r"(a[2]), "r"(a[3]),                \
                   "r"(b0v), "r"(b1v))

// ---------------------------------------------------------------------------
// fp16 mma GEMM with fused epilogue. CUTLASS-shape: block 128x256x32,
// 8 warps (2 x 4), warp tile 64x64, 4-stage cp.async. K = N = 2048.
// smem rows are 64B (BK=32 halves); swizzle: chunk ^= (row>>1)&3.
// MODE 0 (Q): rope -> fp16 (B,H,S,hd)
// MODE 1 (K): rope -> fp16 + fp32 (B,H,S,hd)
// MODE 2 (V): plain -> fp16 + fp32 (B,H,S,hd)
// MODE 3 (O): plain fp32 (B,S,D)
// ---------------------------------------------------------------------------
#define BM 128
#define BN 256
#define BK 32
#define NSTAGE 4
#define A_BYTES (BM * BK * 2)                  // 8192
#define B_BYTES (BN * BK * 2)                  // 16384
#define STAGE_BYTES (A_BYTES + B_BYTES)        // 24576
#define GEMM_SMEM (NSTAGE * STAGE_BYTES)       // 98304

__device__ __forceinline__ uint32_t swz64(int row, int ch) {
    return (uint32_t)(row * 64 + (((ch ^ ((row >> 1) & 3)) & 3) << 4));
}

template <int MODE>
__global__ __launch_bounds__(256, 1)
void gemm_f16(const __half* __restrict__ A, const __half* __restrict__ W,
              float* __restrict__ C32, __half* __restrict__ C16,
              const float* __restrict__ cosT, const float* __restrict__ sinT) {
    extern __shared__ char smem_raw[];
    const uint32_t sbase = (uint32_t)__cvta_generic_to_shared(smem_raw);

    const int K = D_, N = D_;
    const int tid = threadIdx.x;
    const int lane = tid & 31;
    const int warp = tid >> 5;
    const int wm = warp >> 2;        // 0..1  (m slab of 64)
    const int wn = warp & 3;         // 0..3  (n slab of 64)

    const int rowBase = blockIdx.y * BM;
    const int colBase = blockIdx.x * BN;

    // loader mapping: thread t -> row t>>2, chunk t&3 (16B each)
    const int ldRow = tid >> 2;      // 0..63
    const int ldCh = tid & 3;
    const __half* Ag = A + (size_t)rowBase * K + ldCh * 8;
    const __half* Wg = W + (size_t)colBase * K + ldCh * 8;

    const int KT = K / BK;           // 64

    auto load_stage = [&](int kt, int stg) {
        uint32_t sA = sbase + stg * STAGE_BYTES;
        uint32_t sB = sA + A_BYTES;
        const size_t koff = (size_t)kt * BK;
#pragma unroll
        for (int i = 0; i < 2; i++) {              // A: 128 rows
            int r = ldRow + i * 64;
            uint64_t g = __cvta_generic_to_global(Ag + (size_t)r * K + koff);
            asm volatile("cp.async.cg.shared.global [%0], [%1], 16;"
                         :: "r"(sA + swz64(r, ldCh)), "l"(g));
        }
#pragma unroll
        for (int i = 0; i < 4; i++) {              // B: 256 rows
            int r = ldRow + i * 64;
            uint64_t g = __cvta_generic_to_global(Wg + (size_t)r * K + koff);
            asm volatile("cp.async.cg.shared.global [%0], [%1], 16;"
                         :: "r"(sB + swz64(r, ldCh)), "l"(g));
        }
    };

    float acc[4][8][4];
#pragma unroll
    for (int i = 0; i < 4; i++)
#pragma unroll
        for (int j = 0; j < 8; j++)
#pragma unroll
            for (int r = 0; r < 4; r++) acc[i][j][r] = 0.f;

#pragma unroll
    for (int s = 0; s < NSTAGE - 1; s++) {
        load_stage(s, s);
        asm volatile("cp.async.commit_group;" ::: "memory");
    }

    for (int kt = 0; kt < KT; kt++) {
        asm volatile("cp.async.wait_group 2;" ::: "memory");
        __syncthreads();

        const int stg = kt & 3;
        const uint32_t sA = sbase + stg * STAGE_BYTES;
        const uint32_t sB = sA + A_BYTES;

#pragma unroll
        for (int ks = 0; ks < 2; ks++) {           // two k16 steps
            uint32_t a[4][4];
#pragma unroll
            for (int mt = 0; mt < 4; mt++) {
                int row = wm * 64 + mt * 16 + (lane & 15);
                int ch = ks * 2 + (lane >> 4);
                LDMX4(a[mt][0], a[mt][1], a[mt][2], a[mt][3], sA + swz64(row, ch));
            }
            uint32_t b[4][4];
#pragma unroll
            for (int nb = 0; nb < 4; nb++) {
                int row = wn * 64 + nb * 16 + (lane & 7) + ((lane >> 4) & 1) * 8;
                int ch = ks * 2 + ((lane >> 3) & 1);
                LDMX4(b[nb][0], b[nb][1], b[nb][2], b[nb][3], sB + swz64(row, ch));
            }
#pragma unroll
            for (int mt = 0; mt < 4; mt++)
#pragma unroll
                for (int nb = 0; nb < 4; nb++) {
                    MMA_F16(acc[mt][nb * 2 + 0], a[mt], b[nb][0], b[nb][1]);
                    MMA_F16(acc[mt][nb * 2 + 1], a[mt], b[nb][2], b[nb][3]);
                }
        }

        if (kt + NSTAGE - 1 < KT) load_stage(kt + NSTAGE - 1, (kt + NSTAGE - 1) & 3);
        asm volatile("cp.async.commit_group;" ::: "memory");
    }

    // ------------- fused epilogue -------------
    const int erow = lane >> 2;
    const int ecol = (lane & 3) * 2;

#pragma unroll
    for (int mt = 0; mt < 4; mt++) {
#pragma unroll
        for (int n8 = 0; n8 < 8; n8++) {
            const int r0 = rowBase + wm * 64 + mt * 16 + erow;
            const int c0 = colBase + wn * 64 + n8 * 8 + ecol;
            float v[4] = {acc[mt][n8][0], acc[mt][n8][1], acc[mt][n8][2], acc[mt][n8][3]};

            if (MODE == 3) {
                *(float2*)&C32[(size_t)r0 * N + c0] = make_float2(v[0], v[1]);
                *(float2*)&C32[(size_t)(r0 + 8) * N + c0] = make_float2(v[2], v[3]);
            } else {
                const int h = c0 >> 7;
                const int d = c0 & 127;
                const int dp = d >> 1;
#pragma unroll
                for (int rr = 0; rr < 2; rr++) {
                    const int r = r0 + rr * 8;
                    const int b = r >> 11;
                    const int s = r & (S_ - 1);
                    float y0 = v[rr * 2], y1 = v[rr * 2 + 1];
                    if (MODE == 0 || MODE == 1) {
                        float c  = __ldg(&cosT[s * (HD_ / 2) + dp]);
                        float sn = __ldg(&sinT[s * (HD_ / 2) + dp]);
                        float t0 = y0 * c - y1 * sn;
                        float t1 = y0 * sn + y1 * c;
                        y0 = t0; y1 = t1;
                    }
                    const size_t off = ((size_t)(b * H_ + h) * S_ + s) * HD_ + d;
                    *(__half2*)&C16[off] = __floats2half2_rn(y0, y1);
                    if (MODE == 1 || MODE == 2)
                        *(float2*)&C32[off] = make_float2(y0, y1);
                }
            }
        }
    }
}

// ---------------------------------------------------------------------------
// fp16 tensor-core flash attention (causal) — unchanged from R6 (passing).
// ---------------------------------------------------------------------------
#define AQ_B 16384                 // 64 x 256B
#define AK_B 16384
#define AV_B 16384
#define AP_B 8192                  // 64 x 128B
#define ATTN_SMEM (AQ_B + 2*AK_B + 2*AV_B + AP_B)   // 90112

__global__ __launch_bounds__(128, 2)
void flash_attn_f16(const __half* __restrict__ Q, const __half* __restrict__ K,
                    const __half* __restrict__ V, __half* __restrict__ O) {
    extern __shared__ char asmem[];
    const uint32_t sb = (uint32_t)__cvta_generic_to_shared(asmem);
    const uint32_t sQ = sb;
    const uint32_t sK0 = sb + AQ_B;
    const uint32_t sV0 = sb + AQ_B + 2 * AK_B;
    const uint32_t sP = sb + AQ_B + 2 * AK_B + 2 * AV_B;

    const int bh = blockIdx.y;
    const int b = bh >> 4, h = bh & 15;
    const int qt = gridDim.x - 1 - blockIdx.x;
    const int q0 = qt * 64;
    const int nT = qt + 1;

    const int tid = threadIdx.x;
    const int lane = tid & 31;
    const int warp = tid >> 5;

    const __half* Qg = Q + ((size_t)bh * S_ + q0) * HD_;
    const __half* Kg = K + (size_t)bh * S_ * HD_;
    const __half* Vg = V + (size_t)bh * S_ * HD_;

    const int lr = tid >> 1;
    const int lc0 = (tid & 1) * 8;

#pragma unroll
    for (int c = 0; c < 8; c++) {
        int ch = lc0 + c;
        uint32_t off = (uint32_t)(lr * 256 + ((ch ^ (lr & 7)) << 4));
        uint64_t g = __cvta_generic_to_global(Qg + (size_t)lr * HD_ + ch * 8);
        asm volatile("cp.async.cg.shared.global [%0], [%1], 16;" :: "r"(sQ + off), "l"(g));
    }

    auto loadKV = [&](int t) {
        const int j0 = t * 64;
        uint32_t kdst = sK0 + (t & 1) * AK_B;
        uint32_t vdst = sV0 + (t & 1) * AV_B;
#pragma unroll
        for (int c = 0; c < 8; c++) {
            int ch = lc0 + c;
            uint32_t off = (uint32_t)(lr * 256 + ((ch ^ (lr & 7)) << 4));
            uint64_t gk = __cvta_generic_to_global(Kg + (size_t)(j0 + lr) * HD_ + ch * 8);
            uint64_t gv = __cvta_generic_to_global(Vg + (size_t)(j0 + lr) * HD_ + ch * 8);
            asm volatile("cp.async.cg.shared.global [%0], [%1], 16;" :: "r"(kdst + off), "l"(gk));
            asm volatile("cp.async.cg.shared.global [%0], [%1], 16;" :: "r"(vdst + off), "l"(gv));
        }
    };

    loadKV(0);
    asm volatile("cp.async.commit_group;" ::: "memory");
    if (nT > 1) loadKV(1);
    asm volatile("cp.async.commit_group;" ::: "memory");

    const float scale = 0.08838834764831845f;
    float m0 = -INFINITY, m1 = -INFINITY, l0 = 0.f, l1 = 0.f;
    float o[16][4];
#pragma unroll
    for (int i = 0; i < 16; i++)
#pragma unroll
        for (int r = 0; r < 4; r++) o[i][r] = 0.f;

    const int rloc = lane >> 2;
    const int cloc = (lane & 3) * 2;

    for (int t = 0; t < nT; t++) {
        asm volatile("cp.async.wait_group 1;" ::: "memory");
        __syncthreads();
        const uint32_t kb = sK0 + (t & 1) * AK_B;
        const uint32_t vb = sV0 + (t & 1) * AV_B;

        float s[8][4];
#pragma unroll
        for (int nt = 0; nt < 8; nt++)
#pragma unroll
            for (int r = 0; r < 4; r++) s[nt][r] = 0.f;

#pragma unroll
        for (int ks = 0; ks < 8; ks++) {
            uint32_t a[4];
            {
                int row = warp * 16 + (lane & 15);
                int ch = ks * 2 + (lane >> 4);
                uint32_t addr = sQ + row * 256 + ((ch ^ (row & 7)) << 4);
                LDMX4(a[0], a[1], a[2], a[3], addr);
            }
#pragma unroll
            for (int nb = 0; nb < 4; nb++) {
                uint32_t bf[4];
                int row = nb * 16 + (lane & 7) + ((lane >> 4) & 1) * 8;
                int ch = ks * 2 + ((lane >> 3) & 1);
                uint32_t addr = kb + row * 256 + ((ch ^ (row & 7)) << 4);
                LDMX4(bf[0], bf[1], bf[2], bf[3], addr);
                MMA_F16(s[nb * 2 + 0], a, bf[0], bf[1]);
                MMA_F16(s[nb * 2 + 1], a, bf[2], bf[3]);
            }
        }

        const int r0g = q0 + warp * 16 + rloc;
        const bool diag = (t == nT - 1);
#pragma unroll
        for (int nt = 0; nt < 8; nt++) {
#pragma unroll
            for (int r = 0; r < 4; r++) s[nt][r] *= scale;
            if (diag) {
                int colg = t * 64 + nt * 8 + cloc;
                if (colg     > r0g)     s[nt][0] = -1e30f;
                if (colg + 1 > r0g)     s[nt][1] = -1e30f;
                if (colg     > r0g + 8) s[nt][2] = -1e30f;
                if (colg + 1 > r0g + 8) s[nt][3] = -1e30f;
            }
        }
        float vm0 = -1e30f, vm1 = -1e30f;
#pragma unroll
        for (int nt = 0; nt < 8; nt++) {
            vm0 = fmaxf(vm0, fmaxf(s[nt][0], s[nt][1]));
            vm1 = fmaxf(vm1, fmaxf(s[nt][2], s[nt][3]));
        }
        vm0 = fmaxf(vm0, __shfl_xor_sync(0xffffffffu, vm0, 1));
        vm0 = fmaxf(vm0, __shfl_xor_sync(0xffffffffu, vm0, 2));
        vm1 = fmaxf(vm1, __shfl_xor_sync(0xffffffffu, vm1, 1));
        vm1 = fmaxf(vm1, __shfl_xor_sync(0xffffffffu, vm1, 2));
        const float mn0 = fmaxf(m0, vm0), mn1 = fmaxf(m1, vm1);
        const float cr0 = __expf(m0 - mn0), cr1 = __expf(m1 - mn1);

        float ps0 = 0.f, ps1 = 0.f;
#pragma unroll
        for (int nt = 0; nt < 8; nt++) {
            s[nt][0] = __expf(s[nt][0] - mn0);
            s[nt][1] = __expf(s[nt][1] - mn0);
            s[nt][2] = __expf(s[nt][2] - mn1);
            s[nt][3] = __expf(s[nt][3] - mn1);
            ps0 += s[nt][0] + s[nt][1];
            ps1 += s[nt][2] + s[nt][3];
        }
        ps0 += __shfl_xor_sync(0xffffffffu, ps0, 1);
        ps0 += __shfl_xor_sync(0xffffffffu, ps0, 2);
        ps1 += __shfl_xor_sync(0xffffffffu, ps1, 1);
        ps1 += __shfl_xor_sync(0xffffffffu, ps1, 2);
        l0 = l0 * cr0 + ps0;
        l1 = l1 * cr1 + ps1;
        m0 = mn0; m1 = mn1;
#pragma unroll
        for (int i = 0; i < 16; i++) {
            o[i][0] *= cr0; o[i][1] *= cr0;
            o[i][2] *= cr1; o[i][3] *= cr1;
        }

        {
            const int prow = warp * 16 + rloc;
#pragma unroll
            for (int nt = 0; nt < 8; nt++) {
                __half2 h0 = __floats2half2_rn(s[nt][0], s[nt][1]);
                __half2 h1 = __floats2half2_rn(s[nt][2], s[nt][3]);
                int bytecol = (nt * 8 + cloc) * 2;
                int chk = bytecol >> 4, rem = bytecol & 15;
                uint32_t a0 = sP + prow * 128 + ((chk ^ (prow & 7)) << 4) + rem;
                int prow2 = prow + 8;
                uint32_t a1 = sP + prow2 * 128 + ((chk ^ (prow2 & 7)) << 4) + rem;
                asm volatile("st.shared.b32 [%0], %1;" :: "r"(a0), "r"(*(uint32_t*)&h0) : "memory");
                asm volatile("st.shared.b32 [%0], %1;" :: "r"(a1), "r"(*(uint32_t*)&h1) : "memory");
            }
        }
        __syncwarp();

#pragma unroll
        for (int pp = 0; pp < 4; pp++) {
            uint32_t pa[4];
            {
                int row = warp * 16 + (lane & 15);
                int ch = pp * 2 + (lane >> 4);
                uint32_t addr = sP + row * 128 + ((ch ^ (row & 7)) << 4);
                LDMX4(pa[0], pa[1], pa[2], pa[3], addr);
            }
#pragma unroll
            for (int nb = 0; nb < 8; nb++) {
                uint32_t bf[4];
                int row = pp * 16 + (lane & 7) + ((lane >> 3) & 1) * 8;
                int ch = nb * 2 + ((lane >> 4) & 1);
                uint32_t addr = vb + row * 256 + ((ch ^ (row & 7)) << 4);
                LDMX4T(bf[0], bf[1], bf[2], bf[3], addr);
                MMA_F16(o[nb * 2 + 0], pa, bf[0], bf[1]);
                MMA_F16(o[nb * 2 + 1], pa, bf[2], bf[3]);
            }
        }

        __syncthreads();
        if (t + 2 < nT) loadKV(t + 2);
        asm volatile("cp.async.commit_group;" ::: "memory");
    }

    const float inv0 = 1.f / l0, inv1 = 1.f / l1;
    const int gr0 = q0 + warp * 16 + rloc;
#pragma unroll
    for (int nt = 0; nt < 16; nt++) {
        int col = h * HD_ + nt * 8 + cloc;
        *(__half2*)&O[(size_t)(b * S_ + gr0) * D_ + col] =
            __floats2half2_rn(o[nt][0] * inv0, o[nt][1] * inv0);
        *(__half2*)&O[(size_t)(b * S_ + gr0 + 8) * D_ + col] =
            __floats2half2_rn(o[nt][2] * inv1, o[nt][3] * inv1);
    }
}

// ---------------------------------------------------------------------------
// Launcher
// ---------------------------------------------------------------------------
extern "C" void kernel_launch(void* const* d_in, const int* in_sizes, int n_in,
                              void* d_out, int out_size) {
    const float* hs   = (const float*)d_in[0];
    const float* cosT = (const float*)d_in[1];
    const float* sinT = (const float*)d_in[2];
    const float* wq   = (const float*)d_in[3];
    const float* wk   = (const float*)d_in[4];
    const float* wv   = (const float*)d_in[5];
    const float* wo   = (const float*)d_in[6];

    float* out  = (float*)d_out;
    float* kout = out + (size_t)PER_TENSOR;
    float* vout = out + (size_t)2 * PER_TENSOR;

    __half *hs16, *wq16, *wk16, *wv16, *wo16, *q16, *k16, *v16, *o16;
    cudaGetSymbolAddress((void**)&hs16, g_hs16);
    cudaGetSymbolAddress((void**)&wq16, g_wq16);
    cudaGetSymbolAddress((void**)&wk16, g_wk16);
    cudaGetSymbolAddress((void**)&wv16, g_wv16);
    cudaGetSymbolAddress((void**)&wo16, g_wo16);
    cudaGetSymbolAddress((void**)&q16, g_q16);
    cudaGetSymbolAddress((void**)&k16, g_k16);
    cudaGetSymbolAddress((void**)&v16, g_v16);
    cudaGetSymbolAddress((void**)&o16, g_o16);

    cudaFuncSetAttribute(gemm_f16<0>, cudaFuncAttributeMaxDynamicSharedMemorySize, GEMM_SMEM);
    cudaFuncSetAttribute(gemm_f16<1>, cudaFuncAttributeMaxDynamicSharedMemorySize, GEMM_SMEM);
    cudaFuncSetAttribute(gemm_f16<2>, cudaFuncAttributeMaxDynamicSharedMemorySize, GEMM_SMEM);
    cudaFuncSetAttribute(gemm_f16<3>, cudaFuncAttributeMaxDynamicSharedMemorySize, GEMM_SMEM);
    cudaFuncSetAttribute(flash_attn_f16, cudaFuncAttributeMaxDynamicSharedMemorySize, ATTN_SMEM);

    dim3 gemmGrid(D_ / BN, M_ / BM);   // (8, 32) = 256 CTAs
    dim3 attnGrid(S_ / 64, B_ * H_);   // (32, 32)

    const int cvtN = N4_HS + 4 * N4_W;
    cvt_all_f16<<<(cvtN + 255) / 256, 256>>>(
        (const float4*)hs, (const float4*)wq, (const float4*)wk,
        (const float4*)wv, (const float4*)wo,
        (__half2*)hs16, (__half2*)wq16, (__half2*)wk16,
        (__half2*)wv16, (__half2*)wo16);

    gemm_f16<0><<<gemmGrid, 256, GEMM_SMEM>>>(hs16, wq16, nullptr, q16, cosT, sinT);
    gemm_f16<1><<<gemmGrid, 256, GEMM_SMEM>>>(hs16, wk16, kout, k16, cosT, sinT);
    gemm_f16<2><<<gemmGrid, 256, GEMM_SMEM>>>(hs16, wv16, vout, v16, nullptr, nullptr);
    flash_attn_f16<<<attnGrid, 128, ATTN_SMEM>>>(q16, k16, v16, o16);
    gemm_f16<3><<<gemmGrid, 256, GEMM_SMEM>>>(o16, wo16, out, nullptr, nullptr, nullptr);
}

// round 8
// speedup vs baseline: 11.4657x; 1.0202x over previous
#include <cuda_runtime.h>
#include <cuda_fp16.h>
#include <math.h>
#include <cstdint>

// Problem constants
#define B_  2
#define S_  2048
#define D_  2048
#define H_  16
#define HD_ 128
#define M_  (B_ * S_)               // 4096
#define PER_TENSOR (B_ * S_ * D_)   // 8388608

// ---------------------------------------------------------------------------
// Scratch (device globals — no allocation allowed)
// ---------------------------------------------------------------------------
__device__ __half g_hs16[PER_TENSOR];      // hidden_states fp16
__device__ __half g_wq16[D_ * D_];
__device__ __half g_wk16[D_ * D_];
__device__ __half g_wv16[D_ * D_];
__device__ __half g_wo16[D_ * D_];
__device__ __half g_q16[PER_TENSOR];       // Q roped fp16 (B,H,S,hd)
__device__ __half g_k16[PER_TENSOR];       // K roped fp16 (B,H,S,hd)
__device__ __half g_v16[PER_TENSOR];       // V fp16 (B,H,S,hd)
__device__ __half g_o16[PER_TENSOR];       // attention out fp16 (B,S,D)

// ---------------------------------------------------------------------------
// Segmented fp32 -> fp16 conversion (hs + 4 weights in one launch)
// ---------------------------------------------------------------------------
#define N4_HS (PER_TENSOR / 4)
#define N4_W  (D_ * D_ / 4)

__global__ void cvt_all_f16(const float4* __restrict__ hs,
                            const float4* __restrict__ wq,
                            const float4* __restrict__ wk,
                            const float4* __restrict__ wv,
                            const float4* __restrict__ wo,
                            __half2* __restrict__ hs16,
                            __half2* __restrict__ wq16,
                            __half2* __restrict__ wk16,
                            __half2* __restrict__ wv16,
                            __half2* __restrict__ wo16) {
    int i = blockIdx.x * blockDim.x + threadIdx.x;
    const float4* in; __half2* out; int idx;
    if (i < N4_HS) { in = hs; out = hs16; idx = i; }
    else {
        int j = i - N4_HS;
        int seg = j / N4_W; idx = j % N4_W;
        switch (seg) {
            case 0: in = wq; out = wq16; break;
            case 1: in = wk; out = wk16; break;
            case 2: in = wv; out = wv16; break;
            default: in = wo; out = wo16; break;
        }
    }
    float4 v = in[idx];
    __half2 h0 = __floats2half2_rn(v.x, v.y);
    __half2 h1 = __floats2half2_rn(v.z, v.w);
    *(uint2*)&out[2 * idx] = make_uint2(*(uint32_t*)&h0, *(uint32_t*)&h1);
}

// ---------------------------------------------------------------------------
// mma helpers (fp16, fp32 accumulate)
// ---------------------------------------------------------------------------
#define LDMX4(r0, r1, r2, r3, addr)                                           \
    asm volatile("ldmatrix.sync.aligned.m8n8.x4.shared.b16 {%0,%1,%2,%3}, [%4];" \
                 : "=r"(r0), "=r"(r1), "=r"(r2), "=r"(r3) : "r"(addr))

#define LDMX4T(r0, r1, r2, r3, addr)                                          \
    asm volatile("ldmatrix.sync.aligned.m8n8.x4.trans.shared.b16 {%0,%1,%2,%3}, [%4];" \
                 : "=r"(r0), "=r"(r1), "=r"(r2), "=r"(r3) : "r"(addr))

#define MMA_F16(d, a, b0v, b1v)                                               \
    asm volatile("mma.sync.aligned.m16n8k16.row.col.f32.f16.f16.f32 "         \
                 "{%0,%1,%2,%3}, {%4,%5,%6,%7}, {%8,%9}, {%0,%1,%2,%3};"      \
                 : "+f"(d[0]), "+f"(d[1]), "+f"(d[2]), "+f"(d[3])             \
                 : "r"(a[0]), "r"(a[1]), "r"(a[2]), "r"(a[3]),                \
                   "r"(b0v), "r"(b1v))

#define EX2F(y, x) asm("ex2.approx.f32 %0, %1;" : "=f"(y) : "f"(x))

// ---------------------------------------------------------------------------
// GEMM geometry: block 128x256x32, 8 warps (2x4), warp tile 64x64, 4 stages.
// ---------------------------------------------------------------------------
#define BM 128
#define BN 256
#define BK 32
#define NSTAGE 4
#define A_BYTES (BM * BK * 2)                  // 8192
#define B_BYTES (BN * BK * 2)                  // 16384
#define STAGE_BYTES (A_BYTES + B_BYTES)        // 24576
#define GEMM_SMEM (NSTAGE * STAGE_BYTES)       // 98304

__device__ __forceinline__ uint32_t swz64(int row, int ch) {
    return (uint32_t)(row * 64 + (((ch ^ ((row >> 1) & 3)) & 3) << 4));
}

// Shared mainloop: computes acc for (rowBase, colBase) tile of A @ W^T.
__device__ __forceinline__ void gemm_mainloop(
    const __half* __restrict__ A, const __half* __restrict__ W,
    int rowBase, int colBase, uint32_t sbase,
    int tid, int lane, int wm, int wn, float acc[4][8][4]) {
    const int K = D_;

    const int ldRow = tid >> 2;
    const int ldCh = tid & 3;
    const __half* Ag = A + (size_t)rowBase * K + ldCh * 8;
    const __half* Wg = W + (size_t)colBase * K + ldCh * 8;

    const int KT = K / BK;           // 64

    auto load_stage = [&](int kt, int stg) {
        uint32_t sA = sbase + stg * STAGE_BYTES;
        uint32_t sB = sA + A_BYTES;
        const size_t koff = (size_t)kt * BK;
#pragma unroll
        for (int i = 0; i < 2; i++) {
            int r = ldRow + i * 64;
            uint64_t g = __cvta_generic_to_global(Ag + (size_t)r * K + koff);
            asm volatile("cp.async.cg.shared.global [%0], [%1], 16;"
                         :: "r"(sA + swz64(r, ldCh)), "l"(g));
        }
#pragma unroll
        for (int i = 0; i < 4; i++) {
            int r = ldRow + i * 64;
            uint64_t g = __cvta_generic_to_global(Wg + (size_t)r * K + koff);
            asm volatile("cp.async.cg.shared.global [%0], [%1], 16;"
                         :: "r"(sB + swz64(r, ldCh)), "l"(g));
        }
    };

#pragma unroll
    for (int s = 0; s < NSTAGE - 1; s++) {
        load_stage(s, s);
        asm volatile("cp.async.commit_group;" ::: "memory");
    }

    for (int kt = 0; kt < KT; kt++) {
        asm volatile("cp.async.wait_group 2;" ::: "memory");
        __syncthreads();

        const int stg = kt & 3;
        const uint32_t sA = sbase + stg * STAGE_BYTES;
        const uint32_t sB = sA + A_BYTES;

#pragma unroll
        for (int ks = 0; ks < 2; ks++) {
            uint32_t a[4][4];
#pragma unroll
            for (int mt = 0; mt < 4; mt++) {
                int row = wm * 64 + mt * 16 + (lane & 15);
                int ch = ks * 2 + (lane >> 4);
                LDMX4(a[mt][0], a[mt][1], a[mt][2], a[mt][3], sA + swz64(row, ch));
            }
            uint32_t b[4][4];
#pragma unroll
            for (int nb = 0; nb < 4; nb++) {
                int row = wn * 64 + nb * 16 + (lane & 7) + ((lane >> 4) & 1) * 8;
                int ch = ks * 2 + ((lane >> 3) & 1);
                LDMX4(b[nb][0], b[nb][1], b[nb][2], b[nb][3], sB + swz64(row, ch));
            }
#pragma unroll
            for (int mt = 0; mt < 4; mt++)
#pragma unroll
                for (int nb = 0; nb < 4; nb++) {
                    MMA_F16(acc[mt][nb * 2 + 0], a[mt], b[nb][0], b[nb][1]);
                    MMA_F16(acc[mt][nb * 2 + 1], a[mt], b[nb][2], b[nb][3]);
                }
        }

        if (kt + NSTAGE - 1 < KT) load_stage(kt + NSTAGE - 1, (kt + NSTAGE - 1) & 3);
        asm volatile("cp.async.commit_group;" ::: "memory");
    }
}

// ---------------------------------------------------------------------------
// Fused QKV projection: grid (24, 32). blockIdx.x>>3 selects weight/epilogue.
// seg 0 (Q): rope -> fp16;  seg 1 (K): rope -> fp16+fp32;  seg 2 (V): fp16+fp32
// ---------------------------------------------------------------------------
__global__ __launch_bounds__(256, 1)
void gemm_qkv(const __half* __restrict__ A,
              const __half* __restrict__ Wq, const __half* __restrict__ Wk,
              const __half* __restrict__ Wv,
              __half* __restrict__ Q16, __half* __restrict__ K16,
              __half* __restrict__ V16,
              float* __restrict__ K32, float* __restrict__ V32,
              const float* __restrict__ cosT, const float* __restrict__ sinT) {
    extern __shared__ char smem_raw[];
    const uint32_t sbase = (uint32_t)__cvta_generic_to_shared(smem_raw);

    const int tid = threadIdx.x;
    const int lane = tid & 31;
    const int warp = tid >> 5;
    const int wm = warp >> 2;
    const int wn = warp & 3;

    const int seg = blockIdx.x >> 3;               // 0=Q 1=K 2=V
    const int rowBase = blockIdx.y * BM;
    const int colBase = (blockIdx.x & 7) * BN;

    const __half* W = (seg == 0) ? Wq : (seg == 1) ? Wk : Wv;

    float acc[4][8][4];
#pragma unroll
    for (int i = 0; i < 4; i++)
#pragma unroll
        for (int j = 0; j < 8; j++)
#pragma unroll
            for (int r = 0; r < 4; r++) acc[i][j][r] = 0.f;

    gemm_mainloop(A, W, rowBase, colBase, sbase, tid, lane, wm, wn, acc);

    // epilogue
    __half* C16 = (seg == 0) ? Q16 : (seg == 1) ? K16 : V16;
    float* C32 = (seg == 1) ? K32 : V32;
    const bool doRope = (seg != 2);
    const bool do32 = (seg != 0);

    const int erow = lane >> 2;
    const int ecol = (lane & 3) * 2;

#pragma unroll
    for (int mt = 0; mt < 4; mt++) {
#pragma unroll
        for (int n8 = 0; n8 < 8; n8++) {
            const int r0 = rowBase + wm * 64 + mt * 16 + erow;
            const int c0 = colBase + wn * 64 + n8 * 8 + ecol;
            float v[4] = {acc[mt][n8][0], acc[mt][n8][1], acc[mt][n8][2], acc[mt][n8][3]};
            const int h = c0 >> 7;
            const int d = c0 & 127;
            const int dp = d >> 1;
#pragma unroll
            for (int rr = 0; rr < 2; rr++) {
                const int r = r0 + rr * 8;
                const int b = r >> 11;
                const int s = r & (S_ - 1);
                float y0 = v[rr * 2], y1 = v[rr * 2 + 1];
                if (doRope) {
                    float c  = __ldg(&cosT[s * (HD_ / 2) + dp]);
                    float sn = __ldg(&sinT[s * (HD_ / 2) + dp]);
                    float t0 = y0 * c - y1 * sn;
                    float t1 = y0 * sn + y1 * c;
                    y0 = t0; y1 = t1;
                }
                const size_t off = ((size_t)(b * H_ + h) * S_ + s) * HD_ + d;
                *(__half2*)&C16[off] = __floats2half2_rn(y0, y1);
                if (do32)
                    *(float2*)&C32[off] = make_float2(y0, y1);
            }
        }
    }
}

// ---------------------------------------------------------------------------
// Output projection GEMM: fp32 (B,S,D)
// ---------------------------------------------------------------------------
__global__ __launch_bounds__(256, 1)
void gemm_o(const __half* __restrict__ A, const __half* __restrict__ W,
            float* __restrict__ C32) {
    extern __shared__ char smem_raw[];
    const uint32_t sbase = (uint32_t)__cvta_generic_to_shared(smem_raw);

    const int tid = threadIdx.x;
    const int lane = tid & 31;
    const int warp = tid >> 5;
    const int wm = warp >> 2;
    const int wn = warp & 3;

    const int rowBase = blockIdx.y * BM;
    const int colBase = blockIdx.x * BN;

    float acc[4][8][4];
#pragma unroll
    for (int i = 0; i < 4; i++)
#pragma unroll
        for (int j = 0; j < 8; j++)
#pragma unroll
            for (int r = 0; r < 4; r++) acc[i][j][r] = 0.f;

    gemm_mainloop(A, W, rowBase, colBase, sbase, tid, lane, wm, wn, acc);

    const int erow = lane >> 2;
    const int ecol = (lane & 3) * 2;
#pragma unroll
    for (int mt = 0; mt < 4; mt++) {
#pragma unroll
        for (int n8 = 0; n8 < 8; n8++) {
            int r0 = rowBase + wm * 64 + mt * 16 + erow;
            int c0 = colBase + wn * 64 + n8 * 8 + ecol;
            *(float2*)&C32[(size_t)r0 * D_ + c0] = make_float2(acc[mt][n8][0], acc[mt][n8][1]);
            *(float2*)&C32[(size_t)(r0 + 8) * D_ + c0] = make_float2(acc[mt][n8][2], acc[mt][n8][3]);
        }
    }
}

// ---------------------------------------------------------------------------
// fp16 tensor-core flash attention (causal), log2-domain softmax.
// ---------------------------------------------------------------------------
#define AQ_B 16384                 // 64 x 256B
#define AK_B 16384
#define AV_B 16384
#define AP_B 8192                  // 64 x 128B
#define ATTN_SMEM (AQ_B + 2*AK_B + 2*AV_B + AP_B)   // 90112

__global__ __launch_bounds__(128, 2)
void flash_attn_f16(const __half* __restrict__ Q, const __half* __restrict__ K,
                    const __half* __restrict__ V, __half* __restrict__ O) {
    extern __shared__ char asmem[];
    const uint32_t sb = (uint32_t)__cvta_generic_to_shared(asmem);
    const uint32_t sQ = sb;
    const uint32_t sK0 = sb + AQ_B;
    const uint32_t sV0 = sb + AQ_B + 2 * AK_B;
    const uint32_t sP = sb + AQ_B + 2 * AK_B + 2 * AV_B;

    const int bh = blockIdx.y;
    const int b = bh >> 4, h = bh & 15;
    const int qt = gridDim.x - 1 - blockIdx.x;
    const int q0 = qt * 64;
    const int nT = qt + 1;

    const int tid = threadIdx.x;
    const int lane = tid & 31;
    const int warp = tid >> 5;

    const __half* Qg = Q + ((size_t)bh * S_ + q0) * HD_;
    const __half* Kg = K + (size_t)bh * S_ * HD_;
    const __half* Vg = V + (size_t)bh * S_ * HD_;

    const int lr = tid >> 1;
    const int lc0 = (tid & 1) * 8;

#pragma unroll
    for (int c = 0; c < 8; c++) {
        int ch = lc0 + c;
        uint32_t off = (uint32_t)(lr * 256 + ((ch ^ (lr & 7)) << 4));
        uint64_t g = __cvta_generic_to_global(Qg + (size_t)lr * HD_ + ch * 8);
        asm volatile("cp.async.cg.shared.global [%0], [%1], 16;" :: "r"(sQ + off), "l"(g));
    }

    auto loadKV = [&](int t) {
        const int j0 = t * 64;
        uint32_t kdst = sK0 + (t & 1) * AK_B;
        uint32_t vdst = sV0 + (t & 1) * AV_B;
#pragma unroll
        for (int c = 0; c < 8; c++) {
            int ch = lc0 + c;
            uint32_t off = (uint32_t)(lr * 256 + ((ch ^ (lr & 7)) << 4));
            uint64_t gk = __cvta_generic_to_global(Kg + (size_t)(j0 + lr) * HD_ + ch * 8);
            uint64_t gv = __cvta_generic_to_global(Vg + (size_t)(j0 + lr) * HD_ + ch * 8);
            asm volatile("cp.async.cg.shared.global [%0], [%1], 16;" :: "r"(kdst + off), "l"(gk));
            asm volatile("cp.async.cg.shared.global [%0], [%1], 16;" :: "r"(vdst + off), "l"(gv));
        }
    };

    loadKV(0);
    asm volatile("cp.async.commit_group;" ::: "memory");
    if (nT > 1) loadKV(1);
    asm volatile("cp.async.commit_group;" ::: "memory");

    // softmax in log2 domain: scores pre-multiplied by scale*log2(e)
    const float scaleL2 = 0.08838834764831845f * 1.4426950408889634f;
    float m0 = -INFINITY, m1 = -INFINITY, l0 = 0.f, l1 = 0.f;
    float o[16][4];
#pragma unroll
    for (int i = 0; i < 16; i++)
#pragma unroll
        for (int r = 0; r < 4; r++) o[i][r] = 0.f;

    const int rloc = lane >> 2;
    const int cloc = (lane & 3) * 2;

    for (int t = 0; t < nT; t++) {
        asm volatile("cp.async.wait_group 1;" ::: "memory");
        __syncthreads();
        const uint32_t kb = sK0 + (t & 1) * AK_B;
        const uint32_t vb = sV0 + (t & 1) * AV_B;

        float s[8][4];
#pragma unroll
        for (int nt = 0; nt < 8; nt++)
#pragma unroll
            for (int r = 0; r < 4; r++) s[nt][r] = 0.f;

#pragma unroll
        for (int ks = 0; ks < 8; ks++) {
            uint32_t a[4];
            {
                int row = warp * 16 + (lane & 15);
                int ch = ks * 2 + (lane >> 4);
                uint32_t addr = sQ + row * 256 + ((ch ^ (row & 7)) << 4);
                LDMX4(a[0], a[1], a[2], a[3], addr);
            }
#pragma unroll
            for (int nb = 0; nb < 4; nb++) {
                uint32_t bf[4];
                int row = nb * 16 + (lane & 7) + ((lane >> 4) & 1) * 8;
                int ch = ks * 2 + ((lane >> 3) & 1);
                uint32_t addr = kb + row * 256 + ((ch ^ (row & 7)) << 4);
                LDMX4(bf[0], bf[1], bf[2], bf[3], addr);
                MMA_F16(s[nb * 2 + 0], a, bf[0], bf[1]);
                MMA_F16(s[nb * 2 + 1], a, bf[2], bf[3]);
            }
        }

        const int r0g = q0 + warp * 16 + rloc;
        const bool diag = (t == nT - 1);
#pragma unroll
        for (int nt = 0; nt < 8; nt++) {
#pragma unroll
            for (int r = 0; r < 4; r++) s[nt][r] *= scaleL2;
            if (diag) {
                int colg = t * 64 + nt * 8 + cloc;
                if (colg     > r0g)     s[nt][0] = -1e30f;
                if (colg + 1 > r0g)     s[nt][1] = -1e30f;
                if (colg     > r0g + 8) s[nt][2] = -1e30f;
                if (colg + 1 > r0g + 8) s[nt][3] = -1e30f;
            }
        }
        float vm0 = -1e30f, vm1 = -1e30f;
#pragma unroll
        for (int nt = 0; nt < 8; nt++) {
            vm0 = fmaxf(vm0, fmaxf(s[nt][0], s[nt][1]));
            vm1 = fmaxf(vm1, fmaxf(s[nt][2], s[nt][3]));
        }
        vm0 = fmaxf(vm0, __shfl_xor_sync(0xffffffffu, vm0, 1));
        vm0 = fmaxf(vm0, __shfl_xor_sync(0xffffffffu, vm0, 2));
        vm1 = fmaxf(vm1, __shfl_xor_sync(0xffffffffu, vm1, 1));
        vm1 = fmaxf(vm1, __shfl_xor_sync(0xffffffffu, vm1, 2));
        const float mn0 = fmaxf(m0, vm0), mn1 = fmaxf(m1, vm1);
        float cr0, cr1;
        EX2F(cr0, m0 - mn0);
        EX2F(cr1, m1 - mn1);
        if (m0 == -INFINITY) cr0 = 0.f;
        if (m1 == -INFINITY) cr1 = 0.f;

        float ps0 = 0.f, ps1 = 0.f;
#pragma unroll
        for (int nt = 0; nt < 8; nt++) {
            EX2F(s[nt][0], s[nt][0] - mn0);
            EX2F(s[nt][1], s[nt][1] - mn0);
            EX2F(s[nt][2], s[nt][2] - mn1);
            EX2F(s[nt][3], s[nt][3] - mn1);
            ps0 += s[nt][0] + s[nt][1];
            ps1 += s[nt][2] + s[nt][3];
        }
        ps0 += __shfl_xor_sync(0xffffffffu, ps0, 1);
        ps0 += __shfl_xor_sync(0xffffffffu, ps0, 2);
        ps1 += __shfl_xor_sync(0xffffffffu, ps1, 1);
        ps1 += __shfl_xor_sync(0xffffffffu, ps1, 2);
        l0 = l0 * cr0 + ps0;
        l1 = l1 * cr1 + ps1;
        m0 = mn0; m1 = mn1;
#pragma unroll
        for (int i = 0; i < 16; i++) {
            o[i][0] *= cr0; o[i][1] *= cr0;
            o[i][2] *= cr1; o[i][3] *= cr1;
        }

        {
            const int prow = warp * 16 + rloc;
#pragma unroll
            for (int nt = 0; nt < 8; nt++) {
                __half2 h0 = __floats2half2_rn(s[nt][0], s[nt][1]);
                __half2 h1 = __floats2half2_rn(s[nt][2], s[nt][3]);
                int bytecol = (nt * 8 + cloc) * 2;
                int chk = bytecol >> 4, rem = bytecol & 15;
                uint32_t a0 = sP + prow * 128 + ((chk ^ (prow & 7)) << 4) + rem;
                int prow2 = prow + 8;
                uint32_t a1 = sP + prow2 * 128 + ((chk ^ (prow2 & 7)) << 4) + rem;
                asm volatile("st.shared.b32 [%0], %1;" :: "r"(a0), "r"(*(uint32_t*)&h0) : "memory");
                asm volatile("st.shared.b32 [%0], %1;" :: "r"(a1), "r"(*(uint32_t*)&h1) : "memory");
            }
        }
        __syncwarp();

#pragma unroll
        for (int pp = 0; pp < 4; pp++) {
            uint32_t pa[4];
            {
                int row = warp * 16 + (lane & 15);
                int ch = pp * 2 + (lane >> 4);
                uint32_t addr = sP + row * 128 + ((ch ^ (row & 7)) << 4);
                LDMX4(pa[0], pa[1], pa[2], pa[3], addr);
            }
#pragma unroll
            for (int nb = 0; nb < 8; nb++) {
                uint32_t bf[4];
                int row = pp * 16 + (lane & 7) + ((lane >> 3) & 1) * 8;
                int ch = nb * 2 + ((lane >> 4) & 1);
                uint32_t addr = vb + row * 256 + ((ch ^ (row & 7)) << 4);
                LDMX4T(bf[0], bf[1], bf[2], bf[3], addr);
                MMA_F16(o[nb * 2 + 0], pa, bf[0], bf[1]);
                MMA_F16(o[nb * 2 + 1], pa, bf[2], bf[3]);
            }
        }

        __syncthreads();
        if (t + 2 < nT) loadKV(t + 2);
        asm volatile("cp.async.commit_group;" ::: "memory");
    }

    const float inv0 = 1.f / l0, inv1 = 1.f / l1;
    const int gr0 = q0 + warp * 16 + rloc;
#pragma unroll
    for (int nt = 0; nt < 16; nt++) {
        int col = h * HD_ + nt * 8 + cloc;
        *(__half2*)&O[(size_t)(b * S_ + gr0) * D_ + col] =
            __floats2half2_rn(o[nt][0] * inv0, o[nt][1] * inv0);
        *(__half2*)&O[(size_t)(b * S_ + gr0 + 8) * D_ + col] =
            __floats2half2_rn(o[nt][2] * inv1, o[nt][3] * inv1);
    }
}

// ---------------------------------------------------------------------------
// Launcher
// ---------------------------------------------------------------------------
extern "C" void kernel_launch(void* const* d_in, const int* in_sizes, int n_in,
                              void* d_out, int out_size) {
    const float* hs   = (const float*)d_in[0];
    const float* cosT = (const float*)d_in[1];
    const float* sinT = (const float*)d_in[2];
    const float* wq   = (const float*)d_in[3];
    const float* wk   = (const float*)d_in[4];
    const float* wv   = (const float*)d_in[5];
    const float* wo   = (const float*)d_in[6];

    float* out  = (float*)d_out;
    float* kout = out + (size_t)PER_TENSOR;
    float* vout = out + (size_t)2 * PER_TENSOR;

    __half *hs16, *wq16, *wk16, *wv16, *wo16, *q16, *k16, *v16, *o16;
    cudaGetSymbolAddress((void**)&hs16, g_hs16);
    cudaGetSymbolAddress((void**)&wq16, g_wq16);
    cudaGetSymbolAddress((void**)&wk16, g_wk16);
    cudaGetSymbolAddress((void**)&wv16, g_wv16);
    cudaGetSymbolAddress((void**)&wo16, g_wo16);
    cudaGetSymbolAddress((void**)&q16, g_q16);
    cudaGetSymbolAddress((void**)&k16, g_k16);
    cudaGetSymbolAddress((void**)&v16, g_v16);
    cudaGetSymbolAddress((void**)&o16, g_o16);

    cudaFuncSetAttribute(gemm_qkv, cudaFuncAttributeMaxDynamicSharedMemorySize, GEMM_SMEM);
    cudaFuncSetAttribute(gemm_o, cudaFuncAttributeMaxDynamicSharedMemorySize, GEMM_SMEM);
    cudaFuncSetAttribute(flash_attn_f16, cudaFuncAttributeMaxDynamicSharedMemorySize, ATTN_SMEM);

    dim3 qkvGrid(3 * D_ / BN, M_ / BM);  // (24, 32) = 768 CTAs
    dim3 oGrid(D_ / BN, M_ / BM);        // (8, 32)
    dim3 attnGrid(S_ / 64, B_ * H_);     // (32, 32)

    const int cvtN = N4_HS + 4 * N4_W;
    cvt_all_f16<<<(cvtN + 255) / 256, 256>>>(
        (const float4*)hs, (const float4*)wq, (const float4*)wk,
        (const float4*)wv, (const float4*)wo,
        (__half2*)hs16, (__half2*)wq16, (__half2*)wk16,
        (__half2*)wv16, (__half2*)wo16);

    gemm_qkv<<<qkvGrid, 256, GEMM_SMEM>>>(hs16, wq16, wk16, wv16,
                                          q16, k16, v16, kout, vout, cosT, sinT);
    flash_attn_f16<<<attnGrid, 128, ATTN_SMEM>>>(q16, k16, v16, o16);
    gemm_o<<<oGrid, 256, GEMM_SMEM>>>(o16, wo16, out);
}